// round 8
// baseline (speedup 1.0000x reference)
#include <cuda_runtime.h>
#include <cuda_bf16.h>
#include <math.h>
#include <stdint.h>

// Problem constants
#define Bc   64
#define Tc   1024
#define Hc   256
#define NHc  4
#define DHc  64
#define ELc  768
#define TDc  256           // T - EL
#define QKVC 576           // (2*NH+1)*DH

// ---------------- scratch (device globals; no allocation allowed) -----------
__device__ float g_ceproj[Bc * Hc];
__device__ float g_buf1[Bc * Tc * Hc];
__device__ float g_buf2[(size_t)Bc * Tc * QKVC];
__device__ float g_buf3[Bc * Tc * Hc];
__device__ float g_enr [Bc * Tc * Hc];
__device__ float g_attn[Bc * NHc * TDc * DHc];
__device__ float g_mattn[Bc * TDc * DHc];
__device__ float g_da[Bc * TDc * Hc];
__device__ float g_d2[Bc * TDc * 2 * Hc];
__device__ float g_dx[Bc * TDc * Hc];
__device__ float g_dy[Bc * TDc * Hc];
__device__ float g_dz[Bc * TDc * Hc];

// ======================= helpers ============================================
__device__ __forceinline__ uint32_t smem_to_u32(const void* p) {
    uint32_t a;
    asm("{ .reg .u64 t; cvta.to.shared.u64 t, %1; cvt.u32.u64 %0, t; }"
        : "=r"(a) : "l"(p));
    return a;
}
#define SW128(o) ((o) ^ (((o) >> 3) & 0x70))

__device__ __forceinline__ uint32_t pack_bf16(float a, float b) {
    __nv_bfloat162 h = __floats2bfloat162_rn(a, b);
    return *reinterpret_cast<uint32_t*>(&h);
}
// hi = bf16(x),bf16(y); lo = bf16(x-hi), bf16(y-hi)
__device__ __forceinline__ void split2(float x, float y, uint32_t& hi, uint32_t& lo) {
    float xh = __bfloat162float(__float2bfloat16(x));
    float yh = __bfloat162float(__float2bfloat16(y));
    hi = pack_bf16(x, y);
    lo = pack_bf16(x - xh, y - yh);
}

__device__ __forceinline__ void ldsm_x4(uint32_t& r0, uint32_t& r1,
                                        uint32_t& r2, uint32_t& r3, uint32_t a) {
    asm volatile("ldmatrix.sync.aligned.m8n8.x4.shared.b16 {%0,%1,%2,%3}, [%4];"
        : "=r"(r0), "=r"(r1), "=r"(r2), "=r"(r3) : "r"(a));
}
__device__ __forceinline__ void ldsm_x4t(uint32_t& r0, uint32_t& r1,
                                         uint32_t& r2, uint32_t& r3, uint32_t a) {
    asm volatile("ldmatrix.sync.aligned.m8n8.x4.trans.shared.b16 {%0,%1,%2,%3}, [%4];"
        : "=r"(r0), "=r"(r1), "=r"(r2), "=r"(r3) : "r"(a));
}
__device__ __forceinline__ void mma_bf16(float* c, const uint32_t* a, const uint32_t* b) {
    asm volatile(
        "mma.sync.aligned.m16n8k16.row.col.f32.bf16.bf16.f32 "
        "{%0,%1,%2,%3}, {%4,%5,%6,%7}, {%8,%9}, {%0,%1,%2,%3};"
        : "+f"(c[0]), "+f"(c[1]), "+f"(c[2]), "+f"(c[3])
        : "r"(a[0]), "r"(a[1]), "r"(a[2]), "r"(a[3]), "r"(b[0]), "r"(b[1]));
}

// ============ HMMA GEMM:  Y[M,N] = X[M,K] @ W[N,K]^T  =======================
// bf16 hi/lo split: Y = Xhi*Whi + Xhi*Wlo + Xlo*Whi (error ~2^-16).
// CTA tile 128x64, 8 warps (2x4), warp tile 64x16, K chunks of 64, 2 CTAs/SM.
#define GS_A_HI 0
#define GS_A_LO 16384
#define GS_B_HI 32768
#define GS_B_LO 40960
#define GS_TOTAL 49152

__global__ void __launch_bounds__(256, 2)
mma_gemm_k(const float* __restrict__ X, const float* __restrict__ W,
           const float* __restrict__ bias, float* __restrict__ Y,
           int M, int N, int K, int act, const float* __restrict__ rowadd)
{
    extern __shared__ char smem[];
    const uint32_t sb = smem_to_u32(smem);
    const int tid = threadIdx.x;
    const int wid = tid >> 5, lane = tid & 31;
    const int warp_m = wid >> 2;       // 0..1
    const int warp_n = wid & 3;        // 0..3
    const int row0 = blockIdx.y << 7;
    const int col0 = blockIdx.x << 6;  // 64-wide N tile

    const int ldr  = tid >> 3;          // 0..31
    const int ldc  = (tid & 7) << 3;    // 0,8,...,56

    float acc[4][2][4] = {};

    const int nchunks = K >> 6;
    for (int c = 0; c < nchunks; c++) {
        const int k0 = c << 6;
        if (c) __syncthreads();

        #pragma unroll
        for (int g = 0; g < 4; g++) {
            const int lrow = ldr + (g << 5);
            const int arow = min(row0 + lrow, M - 1);
            const float* Ap = X + (size_t)arow * K + k0 + ldc;
            #pragma unroll
            for (int h = 0; h < 2; h++) {
                const uint32_t off = SW128((uint32_t)(lrow * 128 + (ldc + h * 4) * 2));
                float4 av = *reinterpret_cast<const float4*>(Ap + h * 4);
                uint32_t h0, l0, h1, l1;
                split2(av.x, av.y, h0, l0);
                split2(av.z, av.w, h1, l1);
                *reinterpret_cast<uint2*>(smem + GS_A_HI + off) = make_uint2(h0, h1);
                *reinterpret_cast<uint2*>(smem + GS_A_LO + off) = make_uint2(l0, l1);
            }
        }
        #pragma unroll
        for (int g = 0; g < 2; g++) {
            const int lrow = ldr + (g << 5);
            const int brow = min(col0 + lrow, N - 1);
            const float* Bp = W + (size_t)brow * K + k0 + ldc;
            #pragma unroll
            for (int h = 0; h < 2; h++) {
                const uint32_t off = SW128((uint32_t)(lrow * 128 + (ldc + h * 4) * 2));
                float4 bv = *reinterpret_cast<const float4*>(Bp + h * 4);
                uint32_t h0, l0, h1, l1;
                split2(bv.x, bv.y, h0, l0);
                split2(bv.z, bv.w, h1, l1);
                *reinterpret_cast<uint2*>(smem + GS_B_HI + off) = make_uint2(h0, h1);
                *reinterpret_cast<uint2*>(smem + GS_B_LO + off) = make_uint2(l0, l1);
            }
        }
        __syncthreads();

        #pragma unroll
        for (int ks = 0; ks < 4; ks++) {
            const int kk = ks << 4;

            uint32_t ah[4][4], al[4][4], bh[2][2], bl[2][2];
            {
                const int rr = (lane & 7) + ((lane >> 3) & 1) * 8;
                const int kc = kk + ((lane >> 4) << 3);
                #pragma unroll
                for (int mt = 0; mt < 4; mt++) {
                    const uint32_t off =
                        SW128((uint32_t)((warp_m * 64 + mt * 16 + rr) * 128 + kc * 2));
                    ldsm_x4(ah[mt][0], ah[mt][1], ah[mt][2], ah[mt][3],
                            sb + GS_A_HI + off);
                    ldsm_x4(al[mt][0], al[mt][1], al[mt][2], al[mt][3],
                            sb + GS_A_LO + off);
                }
            }
            {
                const int nr = (lane & 7) + ((lane >> 4) << 3);
                const int kc = kk + ((lane >> 3) & 1) * 8;
                const uint32_t off =
                    SW128((uint32_t)((warp_n * 16 + nr) * 128 + kc * 2));
                uint32_t r0, r1, r2, r3;
                ldsm_x4(r0, r1, r2, r3, sb + GS_B_HI + off);
                bh[0][0] = r0; bh[0][1] = r1; bh[1][0] = r2; bh[1][1] = r3;
                ldsm_x4(r0, r1, r2, r3, sb + GS_B_LO + off);
                bl[0][0] = r0; bl[0][1] = r1; bl[1][0] = r2; bl[1][1] = r3;
            }

            #pragma unroll
            for (int mt = 0; mt < 4; mt++)
                #pragma unroll
                for (int nt = 0; nt < 2; nt++) {
                    mma_bf16(acc[mt][nt], ah[mt], bh[nt]);
                    mma_bf16(acc[mt][nt], ah[mt], bl[nt]);
                    mma_bf16(acc[mt][nt], al[mt], bh[nt]);
                }
        }
    }

    const int r_hi  = lane >> 2;
    const int cpair = (lane & 3) << 1;

    #pragma unroll
    for (int mt = 0; mt < 4; mt++) {
        const int rbase = row0 + warp_m * 64 + mt * 16;
        #pragma unroll
        for (int h = 0; h < 2; h++) {
            const int grow = rbase + r_hi + h * 8;
            if (grow >= M) continue;
            #pragma unroll
            for (int nt = 0; nt < 2; nt++) {
                const int gcol = col0 + warp_n * 16 + nt * 8 + cpair;
                if (gcol >= N) continue;
                float v0 = acc[mt][nt][2 * h];
                float v1 = acc[mt][nt][2 * h + 1];
                if (bias) { v0 += bias[gcol]; v1 += bias[gcol + 1]; }
                if (rowadd) {
                    const size_t rb = (size_t)(grow >> 10) * N;
                    v0 += rowadd[rb + gcol];
                    v1 += rowadd[rb + gcol + 1];
                }
                if (act == 1) {
                    v0 = v0 > 0.f ? v0 : expm1f(v0);
                    v1 = v1 > 0.f ? v1 : expm1f(v1);
                }
                *reinterpret_cast<float2*>(Y + (size_t)grow * N + gcol) =
                    make_float2(v0, v1);
            }
        }
    }
}

// ---------------- fused residual + LayerNorm (N = 256, 1 warp / row) --------
__global__ void ln_k(const float* __restrict__ a, const float* __restrict__ resid,
                     const float* __restrict__ g, const float* __restrict__ b,
                     float* __restrict__ out, int rows, int decmap)
{
    int warp = blockIdx.x * (blockDim.x >> 5) + (threadIdx.x >> 5);
    if (warp >= rows) return;
    int lane = threadIdx.x & 31;

    size_t arow = (size_t)warp * Hc;
    size_t rrow;
    if (decmap) {
        int bb = warp / TDc, tl = warp % TDc;
        rrow = ((size_t)bb * Tc + ELc + tl) * Hc;
    } else {
        rrow = arow;
    }

    float vals[8];
    float s = 0.f, s2 = 0.f;
    #pragma unroll
    for (int i = 0; i < 8; i++) {
        int c = lane + 32 * i;
        float v = a[arow + c] + resid[rrow + c];
        vals[i] = v; s += v; s2 += v * v;
    }
    #pragma unroll
    for (int off = 16; off; off >>= 1) {
        s  += __shfl_xor_sync(0xffffffffu, s,  off);
        s2 += __shfl_xor_sync(0xffffffffu, s2, off);
    }
    float mu  = s  * (1.f / Hc);
    float var = s2 * (1.f / Hc) - mu * mu;
    float inv = rsqrtf(var + 1e-3f);
    #pragma unroll
    for (int i = 0; i < 8; i++) {
        int c = lane + 32 * i;
        out[arow + c] = (vals[i] - mu) * inv * g[c] + b[c];
    }
}

// ---------------- GLU: out[m,c] = y[m,c] * sigmoid(y[m,c+256]) (ld = 512) ---
__global__ void glu_k(const float* __restrict__ y, float* __restrict__ out, int rows)
{
    int idx = blockIdx.x * blockDim.x + threadIdx.x;
    if (idx >= rows * Hc) return;
    int r = idx >> 8, c = idx & 255;
    float av = y[(size_t)r * 512 + c];
    float gv = y[(size_t)r * 512 + 256 + c];
    out[idx] = av / (1.f + expf(-gv));
}

// ============ HMMA flash attention (queries t in [EL, T)) ===================
// Block: (qt, h, b) = 64 queries. 4 warps, warp = 16 q rows x 64 cols.
// S = Q K^T and O += P V both bf16 hi/lo split (3 passes each).
#define AS_QH 0
#define AS_QL 8192
#define AS_KH 16384
#define AS_KL 24576
#define AS_VH 32768
#define AS_VL 40960

__global__ void __launch_bounds__(128, 2)
attn_mma_k(const float* __restrict__ qkv)
{
    __shared__ char smem[49152];
    const uint32_t sb = smem_to_u32(smem);
    const int b = blockIdx.z, h = blockIdx.y, qt = blockIdx.x;
    const int t0 = ELc + (qt << 6);
    const int tid = threadIdx.x;
    const int wid = tid >> 5, lane = tid & 31;

    // loader mapping: 64-col fp32 rows -> thread t: row=t>>1, cols (t&1)*32..+32
    const int lrow = tid >> 1;
    const int lc0  = (tid & 1) << 5;

    // ---- Q tile -> smem hi/lo ----
    {
        const float* qp = qkv + ((size_t)b * Tc + t0 + lrow) * QKVC + h * DHc + lc0;
        #pragma unroll
        for (int i = 0; i < 8; i++) {
            float4 v = *reinterpret_cast<const float4*>(qp + 4 * i);
            const uint32_t off = SW128((uint32_t)(lrow * 128 + (lc0 + 4 * i) * 2));
            uint32_t h0, l0, h1, l1;
            split2(v.x, v.y, h0, l0);
            split2(v.z, v.w, h1, l1);
            *reinterpret_cast<uint2*>(smem + AS_QH + off) = make_uint2(h0, h1);
            *reinterpret_cast<uint2*>(smem + AS_QL + off) = make_uint2(l0, l1);
        }
    }
    __syncthreads();

    // ---- Q fragments resident: qh/ql[ks][4] ----
    uint32_t qh[4][4], ql[4][4];
    {
        const int rr = (lane & 7) + ((lane >> 3) & 1) * 8;
        #pragma unroll
        for (int ks = 0; ks < 4; ks++) {
            const int kc = (ks << 4) + ((lane >> 4) << 3);
            const uint32_t off = SW128((uint32_t)((wid * 16 + rr) * 128 + kc * 2));
            ldsm_x4(qh[ks][0], qh[ks][1], qh[ks][2], qh[ks][3], sb + AS_QH + off);
            ldsm_x4(ql[ks][0], ql[ks][1], ql[ks][2], ql[ks][3], sb + AS_QL + off);
        }
    }

    const int rquad = lane >> 2;        // 0..7
    const int c2    = (lane & 3) << 1;  // 0,2,4,6
    const int rowa  = wid * 16 + rquad; // local q row (and +8)

    float m_a = -INFINITY, m_b = -INFINITY, l_a = 0.f, l_b = 0.f;
    float o[8][4];
    #pragma unroll
    for (int i = 0; i < 8; i++)
        #pragma unroll
        for (int j = 0; j < 4; j++) o[i][j] = 0.f;

    const int nkv = (t0 >> 6) + 1;
    for (int kt = 0; kt < nkv; kt++) {
        const int s0 = kt << 6;
        __syncthreads();
        // ---- K,V tiles -> smem hi/lo ----
        {
            const float* kp = qkv + ((size_t)b * Tc + s0 + lrow) * QKVC
                              + NHc * DHc + h * DHc + lc0;
            const float* vp = qkv + ((size_t)b * Tc + s0 + lrow) * QKVC
                              + 2 * NHc * DHc + lc0;
            #pragma unroll
            for (int i = 0; i < 8; i++) {
                const uint32_t off = SW128((uint32_t)(lrow * 128 + (lc0 + 4 * i) * 2));
                float4 kv4 = *reinterpret_cast<const float4*>(kp + 4 * i);
                uint32_t h0, l0, h1, l1;
                split2(kv4.x, kv4.y, h0, l0);
                split2(kv4.z, kv4.w, h1, l1);
                *reinterpret_cast<uint2*>(smem + AS_KH + off) = make_uint2(h0, h1);
                *reinterpret_cast<uint2*>(smem + AS_KL + off) = make_uint2(l0, l1);
                float4 vv4 = *reinterpret_cast<const float4*>(vp + 4 * i);
                split2(vv4.x, vv4.y, h0, l0);
                split2(vv4.z, vv4.w, h1, l1);
                *reinterpret_cast<uint2*>(smem + AS_VH + off) = make_uint2(h0, h1);
                *reinterpret_cast<uint2*>(smem + AS_VL + off) = make_uint2(l0, l1);
            }
        }
        __syncthreads();

        // ---- S = Q K^T ----
        float sf[8][4];
        #pragma unroll
        for (int i = 0; i < 8; i++)
            #pragma unroll
            for (int j = 0; j < 4; j++) sf[i][j] = 0.f;

        #pragma unroll
        for (int ks = 0; ks < 4; ks++) {
            const int nr = (lane & 7) + ((lane >> 4) << 3);
            const int kc = (ks << 4) + ((lane >> 3) & 1) * 8;
            #pragma unroll
            for (int pp = 0; pp < 4; pp++) {
                const uint32_t off = SW128((uint32_t)((pp * 16 + nr) * 128 + kc * 2));
                uint32_t kh0, kh1, kh2, kh3, kl0, kl1, kl2, kl3;
                ldsm_x4(kh0, kh1, kh2, kh3, sb + AS_KH + off);
                ldsm_x4(kl0, kl1, kl2, kl3, sb + AS_KL + off);
                uint32_t b0h[2] = {kh0, kh1}, b1h[2] = {kh2, kh3};
                uint32_t b0l[2] = {kl0, kl1}, b1l[2] = {kl2, kl3};
                mma_bf16(sf[2*pp],   qh[ks], b0h);
                mma_bf16(sf[2*pp],   qh[ks], b0l);
                mma_bf16(sf[2*pp],   ql[ks], b0h);
                mma_bf16(sf[2*pp+1], qh[ks], b1h);
                mma_bf16(sf[2*pp+1], qh[ks], b1l);
                mma_bf16(sf[2*pp+1], ql[ks], b1h);
            }
        }

        // ---- scale + causal mask (only diagonal tile) ----
        const bool diag = (s0 == t0);
        #pragma unroll
        for (int nb = 0; nb < 8; nb++) {
            #pragma unroll
            for (int e = 0; e < 4; e++) {
                float sv = sf[nb][e] * 0.125f;
                if (diag) {
                    const int col = nb * 8 + c2 + (e & 1);
                    const int row = rowa + ((e >> 1) << 3);
                    if (col > row) sv = -INFINITY;
                }
                sf[nb][e] = sv;
            }
        }

        // ---- online softmax ----
        float ma_t = -INFINITY, mb_t = -INFINITY;
        #pragma unroll
        for (int nb = 0; nb < 8; nb++) {
            ma_t = fmaxf(ma_t, fmaxf(sf[nb][0], sf[nb][1]));
            mb_t = fmaxf(mb_t, fmaxf(sf[nb][2], sf[nb][3]));
        }
        ma_t = fmaxf(ma_t, __shfl_xor_sync(0xffffffffu, ma_t, 1));
        ma_t = fmaxf(ma_t, __shfl_xor_sync(0xffffffffu, ma_t, 2));
        mb_t = fmaxf(mb_t, __shfl_xor_sync(0xffffffffu, mb_t, 1));
        mb_t = fmaxf(mb_t, __shfl_xor_sync(0xffffffffu, mb_t, 2));

        const float mna = fmaxf(m_a, ma_t);
        const float mnb = fmaxf(m_b, mb_t);
        const float alpha_a = __expf(m_a - mna);
        const float alpha_b = __expf(m_b - mnb);
        m_a = mna; m_b = mnb;

        float sa = 0.f, sb_ = 0.f;
        #pragma unroll
        for (int nb = 0; nb < 8; nb++) {
            sf[nb][0] = __expf(sf[nb][0] - mna);
            sf[nb][1] = __expf(sf[nb][1] - mna);
            sf[nb][2] = __expf(sf[nb][2] - mnb);
            sf[nb][3] = __expf(sf[nb][3] - mnb);
            sa  += sf[nb][0] + sf[nb][1];
            sb_ += sf[nb][2] + sf[nb][3];
        }
        sa  += __shfl_xor_sync(0xffffffffu, sa, 1);
        sa  += __shfl_xor_sync(0xffffffffu, sa, 2);
        sb_ += __shfl_xor_sync(0xffffffffu, sb_, 1);
        sb_ += __shfl_xor_sync(0xffffffffu, sb_, 2);
        l_a = l_a * alpha_a + sa;
        l_b = l_b * alpha_b + sb_;
        #pragma unroll
        for (int db = 0; db < 8; db++) {
            o[db][0] *= alpha_a; o[db][1] *= alpha_a;
            o[db][2] *= alpha_b; o[db][3] *= alpha_b;
        }

        // ---- O += P V  (P repacked from accum frags, hi/lo) ----
        #pragma unroll
        for (int kb = 0; kb < 4; kb++) {
            uint32_t pa_h[4], pa_l[4];
            split2(sf[2*kb][0],   sf[2*kb][1],   pa_h[0], pa_l[0]);  // row a, k 2c'
            split2(sf[2*kb][2],   sf[2*kb][3],   pa_h[1], pa_l[1]);  // row b, k 2c'
            split2(sf[2*kb+1][0], sf[2*kb+1][1], pa_h[2], pa_l[2]);  // row a, k 8+2c'
            split2(sf[2*kb+1][2], sf[2*kb+1][3], pa_h[3], pa_l[3]);  // row b, k 8+2c'

            const int vr = kb * 16 + ((lane >> 3) & 1) * 8 + (lane & 7);
            #pragma unroll
            for (int djp = 0; djp < 4; djp++) {
                const int d0 = djp * 16 + ((lane >> 4) << 3);
                const uint32_t off = SW128((uint32_t)(vr * 128 + d0 * 2));
                uint32_t vh0, vh1, vh2, vh3, vl0, vl1, vl2, vl3;
                ldsm_x4t(vh0, vh1, vh2, vh3, sb + AS_VH + off);
                ldsm_x4t(vl0, vl1, vl2, vl3, sb + AS_VL + off);
                uint32_t b0h[2] = {vh0, vh1}, b1h[2] = {vh2, vh3};
                uint32_t b0l[2] = {vl0, vl1}, b1l[2] = {vl2, vl3};
                mma_bf16(o[2*djp],   pa_h, b0h);
                mma_bf16(o[2*djp],   pa_h, b0l);
                mma_bf16(o[2*djp],   pa_l, b0h);
                mma_bf16(o[2*djp+1], pa_h, b1h);
                mma_bf16(o[2*djp+1], pa_h, b1l);
                mma_bf16(o[2*djp+1], pa_l, b1h);
            }
        }
    }

    // ---- write O / l ----
    const float ia = 1.f / l_a;
    const float ib = 1.f / l_b;
    const int tla = (qt << 6) + rowa;
    const size_t basea = (((size_t)b * NHc + h) * TDc + tla) * DHc;
    const size_t baseb = basea + 8 * DHc;
    #pragma unroll
    for (int db = 0; db < 8; db++) {
        *reinterpret_cast<float2*>(g_attn + basea + db * 8 + c2) =
            make_float2(o[db][0] * ia, o[db][1] * ia);
        *reinterpret_cast<float2*>(g_attn + baseb + db * 8 + c2) =
            make_float2(o[db][2] * ib, o[db][3] * ib);
    }
}

// ---------------- mean over heads -------------------------------------------
__global__ void mean_k()
{
    int idx = blockIdx.x * blockDim.x + threadIdx.x;
    if (idx >= Bc * TDc * DHc) return;
    int b = idx / (TDc * DHc);
    int rem = idx % (TDc * DHc);
    float s = 0.f;
    #pragma unroll
    for (int h = 0; h < NHc; h++)
        s += g_attn[((size_t)(b * NHc + h) * TDc * DHc) + rem];
    g_mattn[idx] = s * 0.25f;
}

// ---------------- host orchestration ----------------------------------------
extern "C" void kernel_launch(void* const* d_in, const int* in_sizes, int n_in,
                              void* d_out, int out_size)
{
    const float* TF       = (const float*)d_in[0];
    const float* ce       = (const float*)d_in[1];
    const float* eg_Wa    = (const float*)d_in[2];
    const float* eg_ba    = (const float*)d_in[3];
    const float* eg_Wc    = (const float*)d_in[4];
    const float* eg_Wi    = (const float*)d_in[5];
    const float* eg_bi    = (const float*)d_in[6];
    const float* eg_Wg    = (const float*)d_in[7];
    const float* eg_bg    = (const float*)d_in[8];
    const float* eg_lng   = (const float*)d_in[9];
    const float* eg_lnb   = (const float*)d_in[10];
    const float* att_Wqkv = (const float*)d_in[11];
    const float* att_Wout = (const float*)d_in[12];
    const float* ag_W     = (const float*)d_in[13];
    const float* ag_b     = (const float*)d_in[14];
    const float* aln_g    = (const float*)d_in[15];
    const float* aln_b    = (const float*)d_in[16];
    const float* pg_Wa    = (const float*)d_in[17];
    const float* pg_ba    = (const float*)d_in[18];
    const float* pg_Wi    = (const float*)d_in[19];
    const float* pg_bi    = (const float*)d_in[20];
    const float* pg_Wg    = (const float*)d_in[21];
    const float* pg_bg    = (const float*)d_in[22];
    const float* pg_lng   = (const float*)d_in[23];
    const float* pg_lnb   = (const float*)d_in[24];
    const float* dg_W     = (const float*)d_in[25];
    const float* dg_b     = (const float*)d_in[26];
    const float* dln_g    = (const float*)d_in[27];
    const float* dln_b    = (const float*)d_in[28];

    float *ceproj, *buf1, *buf2, *buf3, *enr, *mattn, *da, *d2, *dx, *dy, *dz;
    cudaGetSymbolAddress((void**)&ceproj, g_ceproj);
    cudaGetSymbolAddress((void**)&buf1,   g_buf1);
    cudaGetSymbolAddress((void**)&buf2,   g_buf2);
    cudaGetSymbolAddress((void**)&buf3,   g_buf3);
    cudaGetSymbolAddress((void**)&enr,    g_enr);
    cudaGetSymbolAddress((void**)&mattn,  g_mattn);
    cudaGetSymbolAddress((void**)&da,     g_da);
    cudaGetSymbolAddress((void**)&d2,     g_d2);
    cudaGetSymbolAddress((void**)&dx,     g_dx);
    cudaGetSymbolAddress((void**)&dy,     g_dy);
    cudaGetSymbolAddress((void**)&dz,     g_dz);

    static int attr_set = 0;
    if (!attr_set) {
        cudaFuncSetAttribute(mma_gemm_k, cudaFuncAttributeMaxDynamicSharedMemorySize,
                             GS_TOTAL);
        attr_set = 1;
    }

    const int Menc = Bc * Tc;     // 65536
    const int Mdec = Bc * TDc;    // 16384

    auto gemm = [&](const float* X, const float* W, const float* bias, float* Y,
                    int M, int N, int K, int act, const float* rowadd) {
        dim3 grid((N + 63) / 64, (M + 127) / 128);
        mma_gemm_k<<<grid, 256, GS_TOTAL>>>(X, W, bias, Y, M, N, K, act, rowadd);
    };

    // --- encoder GLU block ---
    gemm(ce, eg_Wc, nullptr, ceproj, 64, Hc, Hc, 0, nullptr);
    gemm(TF, eg_Wa, eg_ba, buf1, Menc, Hc, Hc, 1, ceproj);
    gemm(buf1, eg_Wi, eg_bi, buf3, Menc, Hc, Hc, 0, nullptr);
    gemm(buf3, eg_Wg, eg_bg, buf2, Menc, 2 * Hc, Hc, 0, nullptr);
    glu_k<<<Menc, 256>>>(buf2, buf1, Menc);
    ln_k<<<Menc / 8, 256>>>(buf1, TF, eg_lng, eg_lnb, enr, Menc, 0);

    // --- attention (decoder queries only) ---
    gemm(enr, att_Wqkv, nullptr, buf2, Menc, QKVC, Hc, 0, nullptr);
    attn_mma_k<<<dim3(TDc / 64, NHc, Bc), 128>>>(buf2);
    mean_k<<<(Bc * TDc * DHc) / 256, 256>>>();
    gemm(mattn, att_Wout, nullptr, da, Mdec, Hc, DHc, 0, nullptr);

    // --- decoder ---
    gemm(da, ag_W, ag_b, d2, Mdec, 2 * Hc, Hc, 0, nullptr);
    glu_k<<<Mdec, 256>>>(d2, dx, Mdec);
    ln_k<<<Mdec / 8, 256>>>(dx, enr, aln_g, aln_b, dy, Mdec, 1);

    gemm(dy, pg_Wa, pg_ba, dx, Mdec, Hc, Hc, 1, nullptr);
    gemm(dx, pg_Wi, pg_bi, dz, Mdec, Hc, Hc, 0, nullptr);
    gemm(dz, pg_Wg, pg_bg, d2, Mdec, 2 * Hc, Hc, 0, nullptr);
    glu_k<<<Mdec, 256>>>(d2, dx, Mdec);
    ln_k<<<Mdec / 8, 256>>>(dx, dy, pg_lng, pg_lnb, dz, Mdec, 0);

    gemm(dz, dg_W, dg_b, d2, Mdec, 2 * Hc, Hc, 0, nullptr);
    glu_k<<<Mdec, 256>>>(d2, dx, Mdec);
    ln_k<<<Mdec / 8, 256>>>(dx, TF, dln_g, dln_b, (float*)d_out, Mdec, 1);
}

// round 9
// speedup vs baseline: 1.5736x; 1.5736x over previous
#include <cuda_runtime.h>
#include <cuda_bf16.h>
#include <math.h>
#include <stdint.h>

// Problem constants
#define Bc   64
#define Tc   1024
#define Hc   256
#define NHc  4
#define DHc  64
#define ELc  768
#define TDc  256           // T - EL
#define QKVC 576           // (2*NH+1)*DH

// ---------------- scratch (device globals; no allocation allowed) -----------
__device__ float g_ceproj[Bc * Hc];
__device__ float g_buf1[Bc * Tc * Hc];
__device__ float g_buf2[(size_t)Bc * Tc * 2 * Hc];
__device__ float g_buf3[Bc * Tc * Hc];
__device__ float g_enr [Bc * Tc * Hc];
__device__ __nv_bfloat16 g_qkv_hi[(size_t)Bc * Tc * QKVC];
__device__ __nv_bfloat16 g_qkv_lo[(size_t)Bc * Tc * QKVC];
__device__ float g_attn[Bc * NHc * TDc * DHc];
__device__ float g_mattn[Bc * TDc * DHc];
__device__ float g_da[Bc * TDc * Hc];
__device__ float g_d2[Bc * TDc * 2 * Hc];
__device__ float g_dx[Bc * TDc * Hc];
__device__ float g_dy[Bc * TDc * Hc];
__device__ float g_dz[Bc * TDc * Hc];

// ======================= helpers ============================================
__device__ __forceinline__ uint32_t smem_to_u32(const void* p) {
    uint32_t a;
    asm("{ .reg .u64 t; cvta.to.shared.u64 t, %1; cvt.u32.u64 %0, t; }"
        : "=r"(a) : "l"(p));
    return a;
}
#define SW128(o) ((o) ^ (((o) >> 3) & 0x70))

__device__ __forceinline__ uint32_t pack_bf16(float a, float b) {
    __nv_bfloat162 h = __floats2bfloat162_rn(a, b);
    return *reinterpret_cast<uint32_t*>(&h);
}
// hi = bf16(x),bf16(y); lo = bf16(x-hi), bf16(y-hi)
__device__ __forceinline__ void split2(float x, float y, uint32_t& hi, uint32_t& lo) {
    float xh = __bfloat162float(__float2bfloat16(x));
    float yh = __bfloat162float(__float2bfloat16(y));
    hi = pack_bf16(x, y);
    lo = pack_bf16(x - xh, y - yh);
}

__device__ __forceinline__ void ldsm_x4(uint32_t& r0, uint32_t& r1,
                                        uint32_t& r2, uint32_t& r3, uint32_t a) {
    asm volatile("ldmatrix.sync.aligned.m8n8.x4.shared.b16 {%0,%1,%2,%3}, [%4];"
        : "=r"(r0), "=r"(r1), "=r"(r2), "=r"(r3) : "r"(a));
}
__device__ __forceinline__ void ldsm_x4t(uint32_t& r0, uint32_t& r1,
                                         uint32_t& r2, uint32_t& r3, uint32_t a) {
    asm volatile("ldmatrix.sync.aligned.m8n8.x4.trans.shared.b16 {%0,%1,%2,%3}, [%4];"
        : "=r"(r0), "=r"(r1), "=r"(r2), "=r"(r3) : "r"(a));
}
__device__ __forceinline__ void mma_bf16(float* c, const uint32_t* a, const uint32_t* b) {
    asm volatile(
        "mma.sync.aligned.m16n8k16.row.col.f32.bf16.bf16.f32 "
        "{%0,%1,%2,%3}, {%4,%5,%6,%7}, {%8,%9}, {%0,%1,%2,%3};"
        : "+f"(c[0]), "+f"(c[1]), "+f"(c[2]), "+f"(c[3])
        : "r"(a[0]), "r"(a[1]), "r"(a[2]), "r"(a[3]), "r"(b[0]), "r"(b[1]));
}

// ============ HMMA GEMM:  Y[M,N] = X[M,K] @ W[N,K]^T  =======================
// bf16 hi/lo split: Y = Xhi*Whi + Xhi*Wlo + Xlo*Whi (error ~2^-16).
// CTA tile 128x64, 8 warps (2x4), warp tile 64x16, K chunks of 64, 2 CTAs/SM.
// If Yhi != null: write bf16 hi/lo planes instead of fp32 Y.
#define GS_A_HI 0
#define GS_A_LO 16384
#define GS_B_HI 32768
#define GS_B_LO 40960
#define GS_TOTAL 49152

__global__ void __launch_bounds__(256, 2)
mma_gemm_k(const float* __restrict__ X, const float* __restrict__ W,
           const float* __restrict__ bias, float* __restrict__ Y,
           int M, int N, int K, int act, const float* __restrict__ rowadd,
           __nv_bfloat16* __restrict__ Yhi, __nv_bfloat16* __restrict__ Ylo)
{
    extern __shared__ char smem[];
    const uint32_t sb = smem_to_u32(smem);
    const int tid = threadIdx.x;
    const int wid = tid >> 5, lane = tid & 31;
    const int warp_m = wid >> 2;       // 0..1
    const int warp_n = wid & 3;        // 0..3
    const int row0 = blockIdx.y << 7;
    const int col0 = blockIdx.x << 6;  // 64-wide N tile

    const int ldr  = tid >> 3;          // 0..31
    const int ldc  = (tid & 7) << 3;    // 0,8,...,56

    float acc[4][2][4] = {};

    const int nchunks = K >> 6;
    for (int c = 0; c < nchunks; c++) {
        const int k0 = c << 6;
        if (c) __syncthreads();

        #pragma unroll
        for (int g = 0; g < 4; g++) {
            const int lrow = ldr + (g << 5);
            const int arow = min(row0 + lrow, M - 1);
            const float* Ap = X + (size_t)arow * K + k0 + ldc;
            #pragma unroll
            for (int h = 0; h < 2; h++) {
                const uint32_t off = SW128((uint32_t)(lrow * 128 + (ldc + h * 4) * 2));
                float4 av = *reinterpret_cast<const float4*>(Ap + h * 4);
                uint32_t h0, l0, h1, l1;
                split2(av.x, av.y, h0, l0);
                split2(av.z, av.w, h1, l1);
                *reinterpret_cast<uint2*>(smem + GS_A_HI + off) = make_uint2(h0, h1);
                *reinterpret_cast<uint2*>(smem + GS_A_LO + off) = make_uint2(l0, l1);
            }
        }
        #pragma unroll
        for (int g = 0; g < 2; g++) {
            const int lrow = ldr + (g << 5);
            const int brow = min(col0 + lrow, N - 1);
            const float* Bp = W + (size_t)brow * K + k0 + ldc;
            #pragma unroll
            for (int h = 0; h < 2; h++) {
                const uint32_t off = SW128((uint32_t)(lrow * 128 + (ldc + h * 4) * 2));
                float4 bv = *reinterpret_cast<const float4*>(Bp + h * 4);
                uint32_t h0, l0, h1, l1;
                split2(bv.x, bv.y, h0, l0);
                split2(bv.z, bv.w, h1, l1);
                *reinterpret_cast<uint2*>(smem + GS_B_HI + off) = make_uint2(h0, h1);
                *reinterpret_cast<uint2*>(smem + GS_B_LO + off) = make_uint2(l0, l1);
            }
        }
        __syncthreads();

        #pragma unroll
        for (int ks = 0; ks < 4; ks++) {
            const int kk = ks << 4;

            uint32_t ah[4][4], al[4][4], bh[2][2], bl[2][2];
            {
                const int rr = (lane & 7) + ((lane >> 3) & 1) * 8;
                const int kc = kk + ((lane >> 4) << 3);
                #pragma unroll
                for (int mt = 0; mt < 4; mt++) {
                    const uint32_t off =
                        SW128((uint32_t)((warp_m * 64 + mt * 16 + rr) * 128 + kc * 2));
                    ldsm_x4(ah[mt][0], ah[mt][1], ah[mt][2], ah[mt][3],
                            sb + GS_A_HI + off);
                    ldsm_x4(al[mt][0], al[mt][1], al[mt][2], al[mt][3],
                            sb + GS_A_LO + off);
                }
            }
            {
                const int nr = (lane & 7) + ((lane >> 4) << 3);
                const int kc = kk + ((lane >> 3) & 1) * 8;
                const uint32_t off =
                    SW128((uint32_t)((warp_n * 16 + nr) * 128 + kc * 2));
                uint32_t r0, r1, r2, r3;
                ldsm_x4(r0, r1, r2, r3, sb + GS_B_HI + off);
                bh[0][0] = r0; bh[0][1] = r1; bh[1][0] = r2; bh[1][1] = r3;
                ldsm_x4(r0, r1, r2, r3, sb + GS_B_LO + off);
                bl[0][0] = r0; bl[0][1] = r1; bl[1][0] = r2; bl[1][1] = r3;
            }

            #pragma unroll
            for (int mt = 0; mt < 4; mt++)
                #pragma unroll
                for (int nt = 0; nt < 2; nt++) {
                    mma_bf16(acc[mt][nt], ah[mt], bh[nt]);
                    mma_bf16(acc[mt][nt], ah[mt], bl[nt]);
                    mma_bf16(acc[mt][nt], al[mt], bh[nt]);
                }
        }
    }

    const int r_hi  = lane >> 2;
    const int cpair = (lane & 3) << 1;

    #pragma unroll
    for (int mt = 0; mt < 4; mt++) {
        const int rbase = row0 + warp_m * 64 + mt * 16;
        #pragma unroll
        for (int h = 0; h < 2; h++) {
            const int grow = rbase + r_hi + h * 8;
            if (grow >= M) continue;
            #pragma unroll
            for (int nt = 0; nt < 2; nt++) {
                const int gcol = col0 + warp_n * 16 + nt * 8 + cpair;
                if (gcol >= N) continue;
                float v0 = acc[mt][nt][2 * h];
                float v1 = acc[mt][nt][2 * h + 1];
                if (bias) { v0 += bias[gcol]; v1 += bias[gcol + 1]; }
                if (rowadd) {
                    const size_t rb = (size_t)(grow >> 10) * N;
                    v0 += rowadd[rb + gcol];
                    v1 += rowadd[rb + gcol + 1];
                }
                if (act == 1) {
                    v0 = v0 > 0.f ? v0 : expm1f(v0);
                    v1 = v1 > 0.f ? v1 : expm1f(v1);
                }
                if (Yhi) {
                    uint32_t hv, lv;
                    split2(v0, v1, hv, lv);
                    *reinterpret_cast<uint32_t*>(Yhi + (size_t)grow * N + gcol) = hv;
                    *reinterpret_cast<uint32_t*>(Ylo + (size_t)grow * N + gcol) = lv;
                } else {
                    *reinterpret_cast<float2*>(Y + (size_t)grow * N + gcol) =
                        make_float2(v0, v1);
                }
            }
        }
    }
}

// ---------------- fused residual + LayerNorm (N = 256, 1 warp / row) --------
__global__ void ln_k(const float* __restrict__ a, const float* __restrict__ resid,
                     const float* __restrict__ g, const float* __restrict__ b,
                     float* __restrict__ out, int rows, int decmap)
{
    int warp = blockIdx.x * (blockDim.x >> 5) + (threadIdx.x >> 5);
    if (warp >= rows) return;
    int lane = threadIdx.x & 31;

    size_t arow = (size_t)warp * Hc;
    size_t rrow;
    if (decmap) {
        int bb = warp / TDc, tl = warp % TDc;
        rrow = ((size_t)bb * Tc + ELc + tl) * Hc;
    } else {
        rrow = arow;
    }

    float vals[8];
    float s = 0.f, s2 = 0.f;
    #pragma unroll
    for (int i = 0; i < 8; i++) {
        int c = lane + 32 * i;
        float v = a[arow + c] + resid[rrow + c];
        vals[i] = v; s += v; s2 += v * v;
    }
    #pragma unroll
    for (int off = 16; off; off >>= 1) {
        s  += __shfl_xor_sync(0xffffffffu, s,  off);
        s2 += __shfl_xor_sync(0xffffffffu, s2, off);
    }
    float mu  = s  * (1.f / Hc);
    float var = s2 * (1.f / Hc) - mu * mu;
    float inv = rsqrtf(var + 1e-3f);
    #pragma unroll
    for (int i = 0; i < 8; i++) {
        int c = lane + 32 * i;
        out[arow + c] = (vals[i] - mu) * inv * g[c] + b[c];
    }
}

// ---------------- GLU: out[m,c] = y[m,c] * sigmoid(y[m,c+256]) (ld = 512) ---
__global__ void glu_k(const float* __restrict__ y, float* __restrict__ out, int rows)
{
    int idx = blockIdx.x * blockDim.x + threadIdx.x;
    if (idx >= rows * Hc) return;
    int r = idx >> 8, c = idx & 255;
    float av = y[(size_t)r * 512 + c];
    float gv = y[(size_t)r * 512 + 256 + c];
    out[idx] = av / (1.f + expf(-gv));
}

// ============ HMMA flash attention (queries t in [EL, T)) ===================
// Reads pre-split bf16 hi/lo QKV planes (written by the QKV GEMM epilogue).
// Block: (qt, h, b) = 64 queries, 4 warps, warp = 16 q rows.
// Q staging area (16KB) is reused for K planes after fragments are resident.
#define AT_KH 0
#define AT_KL 8192
#define AT_VH 16384
#define AT_VL 24576

__global__ void __launch_bounds__(128, 3)
attn_mma_k()
{
    __shared__ char smem[32768];
    const uint32_t sb = smem_to_u32(smem);
    const int b = blockIdx.z, h = blockIdx.y, qt = blockIdx.x;
    const int t0 = ELc + (qt << 6);
    const int tid = threadIdx.x;
    const int wid = tid >> 5, lane = tid & 31;

    // ---- stage Q planes (64 rows x 128B each) ----
    {
        const size_t rowbase = ((size_t)b * Tc + t0) * QKVC + h * DHc;
        #pragma unroll
        for (int i = 0; i < 4; i++) {
            const int idx = tid + (i << 7);          // 0..511
            const int row = idx >> 3, ch = (idx & 7) << 4;
            const uint32_t off = SW128((uint32_t)(row * 128 + ch));
            *reinterpret_cast<uint4*>(smem + off) =
                *reinterpret_cast<const uint4*>(
                    reinterpret_cast<const char*>(g_qkv_hi + rowbase + (size_t)row * QKVC) + ch);
            *reinterpret_cast<uint4*>(smem + 8192 + off) =
                *reinterpret_cast<const uint4*>(
                    reinterpret_cast<const char*>(g_qkv_lo + rowbase + (size_t)row * QKVC) + ch);
        }
    }
    __syncthreads();

    // ---- Q fragments resident ----
    uint32_t qh[4][4], ql[4][4];
    {
        const int rr = (lane & 7) + ((lane >> 3) & 1) * 8;
        #pragma unroll
        for (int ks = 0; ks < 4; ks++) {
            const int kc = (ks << 4) + ((lane >> 4) << 3);
            const uint32_t off = SW128((uint32_t)((wid * 16 + rr) * 128 + kc * 2));
            ldsm_x4(qh[ks][0], qh[ks][1], qh[ks][2], qh[ks][3], sb + off);
            ldsm_x4(ql[ks][0], ql[ks][1], ql[ks][2], ql[ks][3], sb + 8192 + off);
        }
    }
    __syncthreads();   // Q area will be overwritten by K staging

    const int rquad = lane >> 2;        // 0..7
    const int c2    = (lane & 3) << 1;  // 0,2,4,6
    const int rowa  = wid * 16 + rquad;

    float m_a = -INFINITY, m_b = -INFINITY, l_a = 0.f, l_b = 0.f;
    float o[8][4];
    #pragma unroll
    for (int i = 0; i < 8; i++)
        #pragma unroll
        for (int j = 0; j < 4; j++) o[i][j] = 0.f;

    const int nkv = (t0 >> 6) + 1;
    for (int kt = 0; kt < nkv; kt++) {
        const int s0 = kt << 6;
        if (kt) __syncthreads();
        // ---- stage K,V planes (uint4 copies, no conversion) ----
        {
            const size_t rowbase = ((size_t)b * Tc + s0) * QKVC;
            const int kcol = NHc * DHc + h * DHc;
            const int vcol = 2 * NHc * DHc;
            #pragma unroll
            for (int i = 0; i < 4; i++) {
                const int idx = tid + (i << 7);
                const int row = idx >> 3, ch = (idx & 7) << 4;
                const uint32_t off = SW128((uint32_t)(row * 128 + ch));
                const char* rh = reinterpret_cast<const char*>(
                    g_qkv_hi + rowbase + (size_t)row * QKVC);
                const char* rl = reinterpret_cast<const char*>(
                    g_qkv_lo + rowbase + (size_t)row * QKVC);
                *reinterpret_cast<uint4*>(smem + AT_KH + off) =
                    *reinterpret_cast<const uint4*>(rh + kcol * 2 + ch);
                *reinterpret_cast<uint4*>(smem + AT_KL + off) =
                    *reinterpret_cast<const uint4*>(rl + kcol * 2 + ch);
                *reinterpret_cast<uint4*>(smem + AT_VH + off) =
                    *reinterpret_cast<const uint4*>(rh + vcol * 2 + ch);
                *reinterpret_cast<uint4*>(smem + AT_VL + off) =
                    *reinterpret_cast<const uint4*>(rl + vcol * 2 + ch);
            }
        }
        __syncthreads();

        // ---- S = Q K^T ----
        float sf[8][4];
        #pragma unroll
        for (int i = 0; i < 8; i++)
            #pragma unroll
            for (int j = 0; j < 4; j++) sf[i][j] = 0.f;

        #pragma unroll
        for (int ks = 0; ks < 4; ks++) {
            const int nr = (lane & 7) + ((lane >> 4) << 3);
            const int kc = (ks << 4) + ((lane >> 3) & 1) * 8;
            #pragma unroll
            for (int pp = 0; pp < 4; pp++) {
                const uint32_t off = SW128((uint32_t)((pp * 16 + nr) * 128 + kc * 2));
                uint32_t kh0, kh1, kh2, kh3, kl0, kl1, kl2, kl3;
                ldsm_x4(kh0, kh1, kh2, kh3, sb + AT_KH + off);
                ldsm_x4(kl0, kl1, kl2, kl3, sb + AT_KL + off);
                uint32_t b0h[2] = {kh0, kh1}, b1h[2] = {kh2, kh3};
                uint32_t b0l[2] = {kl0, kl1}, b1l[2] = {kl2, kl3};
                mma_bf16(sf[2*pp],   qh[ks], b0h);
                mma_bf16(sf[2*pp],   qh[ks], b0l);
                mma_bf16(sf[2*pp],   ql[ks], b0h);
                mma_bf16(sf[2*pp+1], qh[ks], b1h);
                mma_bf16(sf[2*pp+1], qh[ks], b1l);
                mma_bf16(sf[2*pp+1], ql[ks], b1h);
            }
        }

        // ---- scale + causal mask (only diagonal tile) ----
        const bool diag = (s0 == t0);
        #pragma unroll
        for (int nb = 0; nb < 8; nb++) {
            #pragma unroll
            for (int e = 0; e < 4; e++) {
                float sv = sf[nb][e] * 0.125f;
                if (diag) {
                    const int col = nb * 8 + c2 + (e & 1);
                    const int row = rowa + ((e >> 1) << 3);
                    if (col > row) sv = -INFINITY;
                }
                sf[nb][e] = sv;
            }
        }

        // ---- online softmax ----
        float ma_t = -INFINITY, mb_t = -INFINITY;
        #pragma unroll
        for (int nb = 0; nb < 8; nb++) {
            ma_t = fmaxf(ma_t, fmaxf(sf[nb][0], sf[nb][1]));
            mb_t = fmaxf(mb_t, fmaxf(sf[nb][2], sf[nb][3]));
        }
        ma_t = fmaxf(ma_t, __shfl_xor_sync(0xffffffffu, ma_t, 1));
        ma_t = fmaxf(ma_t, __shfl_xor_sync(0xffffffffu, ma_t, 2));
        mb_t = fmaxf(mb_t, __shfl_xor_sync(0xffffffffu, mb_t, 1));
        mb_t = fmaxf(mb_t, __shfl_xor_sync(0xffffffffu, mb_t, 2));

        const float mna = fmaxf(m_a, ma_t);
        const float mnb = fmaxf(m_b, mb_t);
        const float alpha_a = __expf(m_a - mna);
        const float alpha_b = __expf(m_b - mnb);
        m_a = mna; m_b = mnb;

        float sa = 0.f, sb_ = 0.f;
        #pragma unroll
        for (int nb = 0; nb < 8; nb++) {
            sf[nb][0] = __expf(sf[nb][0] - mna);
            sf[nb][1] = __expf(sf[nb][1] - mna);
            sf[nb][2] = __expf(sf[nb][2] - mnb);
            sf[nb][3] = __expf(sf[nb][3] - mnb);
            sa  += sf[nb][0] + sf[nb][1];
            sb_ += sf[nb][2] + sf[nb][3];
        }
        sa  += __shfl_xor_sync(0xffffffffu, sa, 1);
        sa  += __shfl_xor_sync(0xffffffffu, sa, 2);
        sb_ += __shfl_xor_sync(0xffffffffu, sb_, 1);
        sb_ += __shfl_xor_sync(0xffffffffu, sb_, 2);
        l_a = l_a * alpha_a + sa;
        l_b = l_b * alpha_b + sb_;
        #pragma unroll
        for (int db = 0; db < 8; db++) {
            o[db][0] *= alpha_a; o[db][1] *= alpha_a;
            o[db][2] *= alpha_b; o[db][3] *= alpha_b;
        }

        // ---- O += P V  (P repacked from accum frags, hi/lo) ----
        #pragma unroll
        for (int kb = 0; kb < 4; kb++) {
            uint32_t pa_h[4], pa_l[4];
            split2(sf[2*kb][0],   sf[2*kb][1],   pa_h[0], pa_l[0]);
            split2(sf[2*kb][2],   sf[2*kb][3],   pa_h[1], pa_l[1]);
            split2(sf[2*kb+1][0], sf[2*kb+1][1], pa_h[2], pa_l[2]);
            split2(sf[2*kb+1][2], sf[2*kb+1][3], pa_h[3], pa_l[3]);

            const int vr = kb * 16 + ((lane >> 3) & 1) * 8 + (lane & 7);
            #pragma unroll
            for (int djp = 0; djp < 4; djp++) {
                const int d0 = djp * 16 + ((lane >> 4) << 3);
                const uint32_t off = SW128((uint32_t)(vr * 128 + d0 * 2));
                uint32_t vh0, vh1, vh2, vh3, vl0, vl1, vl2, vl3;
                ldsm_x4t(vh0, vh1, vh2, vh3, sb + AT_VH + off);
                ldsm_x4t(vl0, vl1, vl2, vl3, sb + AT_VL + off);
                uint32_t b0h[2] = {vh0, vh1}, b1h[2] = {vh2, vh3};
                uint32_t b0l[2] = {vl0, vl1}, b1l[2] = {vl2, vl3};
                mma_bf16(o[2*djp],   pa_h, b0h);
                mma_bf16(o[2*djp],   pa_h, b0l);
                mma_bf16(o[2*djp],   pa_l, b0h);
                mma_bf16(o[2*djp+1], pa_h, b1h);
                mma_bf16(o[2*djp+1], pa_h, b1l);
                mma_bf16(o[2*djp+1], pa_l, b1h);
            }
        }
    }

    // ---- write O ----
    const float ia = 1.f / l_a;
    const float ib = 1.f / l_b;
    const int tla = (qt << 6) + rowa;
    const size_t basea = (((size_t)b * NHc + h) * TDc + tla) * DHc;
    const size_t baseb = basea + 8 * DHc;
    #pragma unroll
    for (int db = 0; db < 8; db++) {
        *reinterpret_cast<float2*>(g_attn + basea + db * 8 + c2) =
            make_float2(o[db][0] * ia, o[db][1] * ia);
        *reinterpret_cast<float2*>(g_attn + baseb + db * 8 + c2) =
            make_float2(o[db][2] * ib, o[db][3] * ib);
    }
}

// ---------------- mean over heads -------------------------------------------
__global__ void mean_k()
{
    int idx = blockIdx.x * blockDim.x + threadIdx.x;
    if (idx >= Bc * TDc * DHc) return;
    int b = idx / (TDc * DHc);
    int rem = idx % (TDc * DHc);
    float s = 0.f;
    #pragma unroll
    for (int h = 0; h < NHc; h++)
        s += g_attn[((size_t)(b * NHc + h) * TDc * DHc) + rem];
    g_mattn[idx] = s * 0.25f;
}

// ---------------- host orchestration ----------------------------------------
extern "C" void kernel_launch(void* const* d_in, const int* in_sizes, int n_in,
                              void* d_out, int out_size)
{
    const float* TF       = (const float*)d_in[0];
    const float* ce       = (const float*)d_in[1];
    const float* eg_Wa    = (const float*)d_in[2];
    const float* eg_ba    = (const float*)d_in[3];
    const float* eg_Wc    = (const float*)d_in[4];
    const float* eg_Wi    = (const float*)d_in[5];
    const float* eg_bi    = (const float*)d_in[6];
    const float* eg_Wg    = (const float*)d_in[7];
    const float* eg_bg    = (const float*)d_in[8];
    const float* eg_lng   = (const float*)d_in[9];
    const float* eg_lnb   = (const float*)d_in[10];
    const float* att_Wqkv = (const float*)d_in[11];
    const float* att_Wout = (const float*)d_in[12];
    const float* ag_W     = (const float*)d_in[13];
    const float* ag_b     = (const float*)d_in[14];
    const float* aln_g    = (const float*)d_in[15];
    const float* aln_b    = (const float*)d_in[16];
    const float* pg_Wa    = (const float*)d_in[17];
    const float* pg_ba    = (const float*)d_in[18];
    const float* pg_Wi    = (const float*)d_in[19];
    const float* pg_bi    = (const float*)d_in[20];
    const float* pg_Wg    = (const float*)d_in[21];
    const float* pg_bg    = (const float*)d_in[22];
    const float* pg_lng   = (const float*)d_in[23];
    const float* pg_lnb   = (const float*)d_in[24];
    const float* dg_W     = (const float*)d_in[25];
    const float* dg_b     = (const float*)d_in[26];
    const float* dln_g    = (const float*)d_in[27];
    const float* dln_b    = (const float*)d_in[28];

    float *ceproj, *buf1, *buf2, *buf3, *enr, *mattn, *da, *d2, *dx, *dy, *dz;
    __nv_bfloat16 *qkvh, *qkvl;
    cudaGetSymbolAddress((void**)&ceproj, g_ceproj);
    cudaGetSymbolAddress((void**)&buf1,   g_buf1);
    cudaGetSymbolAddress((void**)&buf2,   g_buf2);
    cudaGetSymbolAddress((void**)&buf3,   g_buf3);
    cudaGetSymbolAddress((void**)&enr,    g_enr);
    cudaGetSymbolAddress((void**)&qkvh,   g_qkv_hi);
    cudaGetSymbolAddress((void**)&qkvl,   g_qkv_lo);
    cudaGetSymbolAddress((void**)&mattn,  g_mattn);
    cudaGetSymbolAddress((void**)&da,     g_da);
    cudaGetSymbolAddress((void**)&d2,     g_d2);
    cudaGetSymbolAddress((void**)&dx,     g_dx);
    cudaGetSymbolAddress((void**)&dy,     g_dy);
    cudaGetSymbolAddress((void**)&dz,     g_dz);

    static int attr_set = 0;
    if (!attr_set) {
        cudaFuncSetAttribute(mma_gemm_k, cudaFuncAttributeMaxDynamicSharedMemorySize,
                             GS_TOTAL);
        attr_set = 1;
    }

    const int Menc = Bc * Tc;     // 65536
    const int Mdec = Bc * TDc;    // 16384

    auto gemm = [&](const float* X, const float* W, const float* bias, float* Y,
                    int M, int N, int K, int act, const float* rowadd,
                    __nv_bfloat16* Yhi = nullptr, __nv_bfloat16* Ylo = nullptr) {
        dim3 grid((N + 63) / 64, (M + 127) / 128);
        mma_gemm_k<<<grid, 256, GS_TOTAL>>>(X, W, bias, Y, M, N, K, act, rowadd,
                                            Yhi, Ylo);
    };

    // --- encoder GLU block ---
    gemm(ce, eg_Wc, nullptr, ceproj, 64, Hc, Hc, 0, nullptr);
    gemm(TF, eg_Wa, eg_ba, buf1, Menc, Hc, Hc, 1, ceproj);
    gemm(buf1, eg_Wi, eg_bi, buf3, Menc, Hc, Hc, 0, nullptr);
    gemm(buf3, eg_Wg, eg_bg, buf2, Menc, 2 * Hc, Hc, 0, nullptr);
    glu_k<<<Menc, 256>>>(buf2, buf1, Menc);
    ln_k<<<Menc / 8, 256>>>(buf1, TF, eg_lng, eg_lnb, enr, Menc, 0);

    // --- attention (decoder queries only) ---
    gemm(enr, att_Wqkv, nullptr, nullptr, Menc, QKVC, Hc, 0, nullptr, qkvh, qkvl);
    attn_mma_k<<<dim3(TDc / 64, NHc, Bc), 128>>>();
    mean_k<<<(Bc * TDc * DHc) / 256, 256>>>();
    gemm(mattn, att_Wout, nullptr, da, Mdec, Hc, DHc, 0, nullptr);

    // --- decoder ---
    gemm(da, ag_W, ag_b, d2, Mdec, 2 * Hc, Hc, 0, nullptr);
    glu_k<<<Mdec, 256>>>(d2, dx, Mdec);
    ln_k<<<Mdec / 8, 256>>>(dx, enr, aln_g, aln_b, dy, Mdec, 1);

    gemm(dy, pg_Wa, pg_ba, dx, Mdec, Hc, Hc, 1, nullptr);
    gemm(dx, pg_Wi, pg_bi, dz, Mdec, Hc, Hc, 0, nullptr);
    gemm(dz, pg_Wg, pg_bg, d2, Mdec, 2 * Hc, Hc, 0, nullptr);
    glu_k<<<Mdec, 256>>>(d2, dx, Mdec);
    ln_k<<<Mdec / 8, 256>>>(dx, dy, pg_lng, pg_lnb, dz, Mdec, 0);

    gemm(dz, dg_W, dg_b, d2, Mdec, 2 * Hc, Hc, 0, nullptr);
    glu_k<<<Mdec, 256>>>(d2, dx, Mdec);
    ln_k<<<Mdec / 8, 256>>>(dx, TF, dln_g, dln_b, (float*)d_out, Mdec, 1);
}

// round 10
// speedup vs baseline: 1.6472x; 1.0468x over previous
#include <cuda_runtime.h>
#include <cuda_bf16.h>
#include <math.h>
#include <stdint.h>

// Problem constants
#define Bc   64
#define Tc   1024
#define Hc   256
#define NHc  4
#define DHc  64
#define ELc  768
#define TDc  256           // T - EL
#define QKVC 576           // (2*NH+1)*DH

// ---------------- scratch (device globals; no allocation allowed) -----------
__device__ float g_ceproj[Bc * Hc];
__device__ float g_buf1[Bc * Tc * Hc];
__device__ float g_buf2[(size_t)Bc * Tc * 2 * Hc];
__device__ float g_enr [Bc * Tc * Hc];
__device__ float g_attn[Bc * NHc * TDc * DHc];
__device__ float g_d2[Bc * TDc * 2 * Hc];
__device__ float g_dx[Bc * TDc * Hc];
__device__ float g_dy[Bc * TDc * Hc];

// bf16 hi/lo plane buffers
__device__ __nv_bfloat16 g_tf_hi[(size_t)Bc * Tc * Hc];
__device__ __nv_bfloat16 g_tf_lo[(size_t)Bc * Tc * Hc];
__device__ __nv_bfloat16 g_ce_hi[Bc * Hc];
__device__ __nv_bfloat16 g_ce_lo[Bc * Hc];
__device__ __nv_bfloat16 g_p1_hi[(size_t)Bc * Tc * Hc];
__device__ __nv_bfloat16 g_p1_lo[(size_t)Bc * Tc * Hc];
__device__ __nv_bfloat16 g_p2_hi[(size_t)Bc * Tc * Hc];
__device__ __nv_bfloat16 g_p2_lo[(size_t)Bc * Tc * Hc];
__device__ __nv_bfloat16 g_qkv_hi[(size_t)Bc * Tc * QKVC];
__device__ __nv_bfloat16 g_qkv_lo[(size_t)Bc * Tc * QKVC];
__device__ __nv_bfloat16 g_mat_hi[Bc * TDc * DHc];
__device__ __nv_bfloat16 g_mat_lo[Bc * TDc * DHc];
#define WTOT 1015808
__device__ __nv_bfloat16 g_w_hi[WTOT];
__device__ __nv_bfloat16 g_w_lo[WTOT];
// weight plane offsets (elements)
#define O_Wa    0
#define O_Wc    65536
#define O_Wi    131072
#define O_Wg    196608
#define O_QKV   327680
#define O_WOUT  475136
#define O_AG    491520
#define O_PGWA  622592
#define O_PGWI  688128
#define O_PGWG  753664
#define O_DG    884736

// ======================= helpers ============================================
__device__ __forceinline__ uint32_t smem_to_u32(const void* p) {
    uint32_t a;
    asm("{ .reg .u64 t; cvta.to.shared.u64 t, %1; cvt.u32.u64 %0, t; }"
        : "=r"(a) : "l"(p));
    return a;
}
#define SW128(o) ((o) ^ (((o) >> 3) & 0x70))

__device__ __forceinline__ uint32_t pack_bf16(float a, float b) {
    __nv_bfloat162 h = __floats2bfloat162_rn(a, b);
    return *reinterpret_cast<uint32_t*>(&h);
}
__device__ __forceinline__ void split2(float x, float y, uint32_t& hi, uint32_t& lo) {
    float xh = __bfloat162float(__float2bfloat16(x));
    float yh = __bfloat162float(__float2bfloat16(y));
    hi = pack_bf16(x, y);
    lo = pack_bf16(x - xh, y - yh);
}

__device__ __forceinline__ void ldsm_x4(uint32_t& r0, uint32_t& r1,
                                        uint32_t& r2, uint32_t& r3, uint32_t a) {
    asm volatile("ldmatrix.sync.aligned.m8n8.x4.shared.b16 {%0,%1,%2,%3}, [%4];"
        : "=r"(r0), "=r"(r1), "=r"(r2), "=r"(r3) : "r"(a));
}
__device__ __forceinline__ void ldsm_x4t(uint32_t& r0, uint32_t& r1,
                                         uint32_t& r2, uint32_t& r3, uint32_t a) {
    asm volatile("ldmatrix.sync.aligned.m8n8.x4.trans.shared.b16 {%0,%1,%2,%3}, [%4];"
        : "=r"(r0), "=r"(r1), "=r"(r2), "=r"(r3) : "r"(a));
}
__device__ __forceinline__ void mma_bf16(float* c, const uint32_t* a, const uint32_t* b) {
    asm volatile(
        "mma.sync.aligned.m16n8k16.row.col.f32.bf16.bf16.f32 "
        "{%0,%1,%2,%3}, {%4,%5,%6,%7}, {%8,%9}, {%0,%1,%2,%3};"
        : "+f"(c[0]), "+f"(c[1]), "+f"(c[2]), "+f"(c[3])
        : "r"(a[0]), "r"(a[1]), "r"(a[2]), "r"(a[3]), "r"(b[0]), "r"(b[1]));
}

// ---------------- fp32 -> bf16 hi/lo plane conversion -----------------------
__global__ void conv_k(const float* __restrict__ x, __nv_bfloat16* __restrict__ hi,
                       __nv_bfloat16* __restrict__ lo, int n4)
{
    int i = blockIdx.x * blockDim.x + threadIdx.x;
    if (i >= n4) return;
    float4 v = reinterpret_cast<const float4*>(x)[i];
    uint32_t h0, l0, h1, l1;
    split2(v.x, v.y, h0, l0);
    split2(v.z, v.w, h1, l1);
    reinterpret_cast<uint2*>(hi)[i] = make_uint2(h0, h1);
    reinterpret_cast<uint2*>(lo)[i] = make_uint2(l0, l1);
}

// ============ HMMA GEMM on pre-split planes =================================
// Y[M,N] = X[M,K] @ W[N,K]^T, X/W given as bf16 hi/lo planes.
// hi*hi + hi*lo + lo*hi (error ~2^-16). CTA tile 128x64, 8 warps, 2 CTAs/SM.
#define GS_A_HI 0
#define GS_A_LO 16384
#define GS_B_HI 32768
#define GS_B_LO 40960
#define GS_TOTAL 49152

__global__ void __launch_bounds__(256, 2)
mma_gemm_k(const __nv_bfloat16* __restrict__ Xhi, const __nv_bfloat16* __restrict__ Xlo,
           const __nv_bfloat16* __restrict__ Whi, const __nv_bfloat16* __restrict__ Wlo,
           const float* __restrict__ bias, float* __restrict__ Y,
           int M, int N, int K, int act, const float* __restrict__ rowadd,
           __nv_bfloat16* __restrict__ Yhi, __nv_bfloat16* __restrict__ Ylo)
{
    extern __shared__ char smem[];
    const uint32_t sb = smem_to_u32(smem);
    const int tid = threadIdx.x;
    const int wid = tid >> 5, lane = tid & 31;
    const int warp_m = wid >> 2;       // 0..1
    const int warp_n = wid & 3;        // 0..3
    const int row0 = blockIdx.y << 7;
    const int col0 = blockIdx.x << 6;  // 64-wide N tile

    float acc[4][2][4] = {};

    const int nchunks = K >> 6;
    for (int c = 0; c < nchunks; c++) {
        const int k0 = c << 6;
        if (c) __syncthreads();

        // ---- A planes: 128 rows x 128B, pure uint4 copies ----
        #pragma unroll
        for (int i = 0; i < 4; i++) {
            const int idx = tid + (i << 8);         // 0..1023
            const int row = idx >> 3, ch = (idx & 7) << 4;
            const int arow = min(row0 + row, M - 1);
            const uint32_t off = SW128((uint32_t)(row * 128 + ch));
            *reinterpret_cast<uint4*>(smem + GS_A_HI + off) =
                *reinterpret_cast<const uint4*>(
                    reinterpret_cast<const char*>(Xhi + (size_t)arow * K + k0) + ch);
            *reinterpret_cast<uint4*>(smem + GS_A_LO + off) =
                *reinterpret_cast<const uint4*>(
                    reinterpret_cast<const char*>(Xlo + (size_t)arow * K + k0) + ch);
        }
        // ---- B planes: 64 rows x 128B ----
        #pragma unroll
        for (int i = 0; i < 2; i++) {
            const int idx = tid + (i << 8);         // 0..511
            const int row = idx >> 3, ch = (idx & 7) << 4;
            const int brow = min(col0 + row, N - 1);
            const uint32_t off = SW128((uint32_t)(row * 128 + ch));
            *reinterpret_cast<uint4*>(smem + GS_B_HI + off) =
                *reinterpret_cast<const uint4*>(
                    reinterpret_cast<const char*>(Whi + (size_t)brow * K + k0) + ch);
            *reinterpret_cast<uint4*>(smem + GS_B_LO + off) =
                *reinterpret_cast<const uint4*>(
                    reinterpret_cast<const char*>(Wlo + (size_t)brow * K + k0) + ch);
        }
        __syncthreads();

        #pragma unroll
        for (int ks = 0; ks < 4; ks++) {
            const int kk = ks << 4;

            uint32_t ah[4][4], al[4][4], bh[2][2], bl[2][2];
            {
                const int rr = (lane & 7) + ((lane >> 3) & 1) * 8;
                const int kc = kk + ((lane >> 4) << 3);
                #pragma unroll
                for (int mt = 0; mt < 4; mt++) {
                    const uint32_t off =
                        SW128((uint32_t)((warp_m * 64 + mt * 16 + rr) * 128 + kc * 2));
                    ldsm_x4(ah[mt][0], ah[mt][1], ah[mt][2], ah[mt][3],
                            sb + GS_A_HI + off);
                    ldsm_x4(al[mt][0], al[mt][1], al[mt][2], al[mt][3],
                            sb + GS_A_LO + off);
                }
            }
            {
                const int nr = (lane & 7) + ((lane >> 4) << 3);
                const int kc = kk + ((lane >> 3) & 1) * 8;
                const uint32_t off =
                    SW128((uint32_t)((warp_n * 16 + nr) * 128 + kc * 2));
                uint32_t r0, r1, r2, r3;
                ldsm_x4(r0, r1, r2, r3, sb + GS_B_HI + off);
                bh[0][0] = r0; bh[0][1] = r1; bh[1][0] = r2; bh[1][1] = r3;
                ldsm_x4(r0, r1, r2, r3, sb + GS_B_LO + off);
                bl[0][0] = r0; bl[0][1] = r1; bl[1][0] = r2; bl[1][1] = r3;
            }

            #pragma unroll
            for (int mt = 0; mt < 4; mt++)
                #pragma unroll
                for (int nt = 0; nt < 2; nt++) {
                    mma_bf16(acc[mt][nt], ah[mt], bh[nt]);
                    mma_bf16(acc[mt][nt], ah[mt], bl[nt]);
                    mma_bf16(acc[mt][nt], al[mt], bh[nt]);
                }
        }
    }

    const int r_hi  = lane >> 2;
    const int cpair = (lane & 3) << 1;

    #pragma unroll
    for (int mt = 0; mt < 4; mt++) {
        const int rbase = row0 + warp_m * 64 + mt * 16;
        #pragma unroll
        for (int h = 0; h < 2; h++) {
            const int grow = rbase + r_hi + h * 8;
            if (grow >= M) continue;
            #pragma unroll
            for (int nt = 0; nt < 2; nt++) {
                const int gcol = col0 + warp_n * 16 + nt * 8 + cpair;
                if (gcol >= N) continue;
                float v0 = acc[mt][nt][2 * h];
                float v1 = acc[mt][nt][2 * h + 1];
                if (bias) { v0 += bias[gcol]; v1 += bias[gcol + 1]; }
                if (rowadd) {
                    const size_t rb = (size_t)(grow >> 10) * N;
                    v0 += rowadd[rb + gcol];
                    v1 += rowadd[rb + gcol + 1];
                }
                if (act == 1) {
                    v0 = v0 > 0.f ? v0 : expm1f(v0);
                    v1 = v1 > 0.f ? v1 : expm1f(v1);
                }
                if (Yhi) {
                    uint32_t hv, lv;
                    split2(v0, v1, hv, lv);
                    *reinterpret_cast<uint32_t*>(Yhi + (size_t)grow * N + gcol) = hv;
                    *reinterpret_cast<uint32_t*>(Ylo + (size_t)grow * N + gcol) = lv;
                }
                if (Y) {
                    *reinterpret_cast<float2*>(Y + (size_t)grow * N + gcol) =
                        make_float2(v0, v1);
                }
            }
        }
    }
}

// ---------------- fused residual + LayerNorm (N = 256, 1 warp / row) --------
// Optional fp32 out and/or bf16 hi/lo plane outputs.
__global__ void ln_k(const float* __restrict__ a, const float* __restrict__ resid,
                     const float* __restrict__ g, const float* __restrict__ b,
                     float* __restrict__ out,
                     __nv_bfloat16* __restrict__ ohi, __nv_bfloat16* __restrict__ olo,
                     int rows, int decmap)
{
    int warp = blockIdx.x * (blockDim.x >> 5) + (threadIdx.x >> 5);
    if (warp >= rows) return;
    int lane = threadIdx.x & 31;

    size_t arow = (size_t)warp * Hc;
    size_t rrow;
    if (decmap) {
        int bb = warp / TDc, tl = warp % TDc;
        rrow = ((size_t)bb * Tc + ELc + tl) * Hc;
    } else {
        rrow = arow;
    }

    float v[8];
    float s = 0.f, s2 = 0.f;
    #pragma unroll
    for (int i = 0; i < 4; i++) {
        int c = lane * 2 + 64 * i;
        float2 av = *reinterpret_cast<const float2*>(a + arow + c);
        float2 rv = *reinterpret_cast<const float2*>(resid + rrow + c);
        v[2*i]   = av.x + rv.x;
        v[2*i+1] = av.y + rv.y;
        s += v[2*i] + v[2*i+1];
        s2 += v[2*i] * v[2*i] + v[2*i+1] * v[2*i+1];
    }
    #pragma unroll
    for (int off = 16; off; off >>= 1) {
        s  += __shfl_xor_sync(0xffffffffu, s,  off);
        s2 += __shfl_xor_sync(0xffffffffu, s2, off);
    }
    float mu  = s  * (1.f / Hc);
    float var = s2 * (1.f / Hc) - mu * mu;
    float inv = rsqrtf(var + 1e-3f);
    #pragma unroll
    for (int i = 0; i < 4; i++) {
        int c = lane * 2 + 64 * i;
        float2 gv = *reinterpret_cast<const float2*>(g + c);
        float2 bv = *reinterpret_cast<const float2*>(b + c);
        float y0 = (v[2*i]   - mu) * inv * gv.x + bv.x;
        float y1 = (v[2*i+1] - mu) * inv * gv.y + bv.y;
        if (out)
            *reinterpret_cast<float2*>(out + arow + c) = make_float2(y0, y1);
        if (ohi) {
            uint32_t hv, lv;
            split2(y0, y1, hv, lv);
            *reinterpret_cast<uint32_t*>(ohi + arow + c) = hv;
            *reinterpret_cast<uint32_t*>(olo + arow + c) = lv;
        }
    }
}

// ---------------- GLU: out[m,c] = y[m,c] * sigmoid(y[m,c+256]) (ld = 512) ---
__global__ void glu_k(const float* __restrict__ y, float* __restrict__ out, int rows)
{
    int idx = blockIdx.x * blockDim.x + threadIdx.x;
    if (idx >= rows * Hc) return;
    int r = idx >> 8, c = idx & 255;
    float av = y[(size_t)r * 512 + c];
    float gv = y[(size_t)r * 512 + 256 + c];
    out[idx] = av / (1.f + expf(-gv));
}

// ============ HMMA flash attention (queries t in [EL, T)) ===================
#define AT_KH 0
#define AT_KL 8192
#define AT_VH 16384
#define AT_VL 24576

__global__ void __launch_bounds__(128, 3)
attn_mma_k()
{
    __shared__ char smem[32768];
    const uint32_t sb = smem_to_u32(smem);
    const int b = blockIdx.z, h = blockIdx.y, qt = blockIdx.x;
    const int t0 = ELc + (qt << 6);
    const int tid = threadIdx.x;
    const int wid = tid >> 5, lane = tid & 31;

    // ---- stage Q planes ----
    {
        const size_t rowbase = ((size_t)b * Tc + t0) * QKVC + h * DHc;
        #pragma unroll
        for (int i = 0; i < 4; i++) {
            const int idx = tid + (i << 7);
            const int row = idx >> 3, ch = (idx & 7) << 4;
            const uint32_t off = SW128((uint32_t)(row * 128 + ch));
            *reinterpret_cast<uint4*>(smem + off) =
                *reinterpret_cast<const uint4*>(
                    reinterpret_cast<const char*>(g_qkv_hi + rowbase + (size_t)row * QKVC) + ch);
            *reinterpret_cast<uint4*>(smem + 8192 + off) =
                *reinterpret_cast<const uint4*>(
                    reinterpret_cast<const char*>(g_qkv_lo + rowbase + (size_t)row * QKVC) + ch);
        }
    }
    __syncthreads();

    uint32_t qh[4][4], ql[4][4];
    {
        const int rr = (lane & 7) + ((lane >> 3) & 1) * 8;
        #pragma unroll
        for (int ks = 0; ks < 4; ks++) {
            const int kc = (ks << 4) + ((lane >> 4) << 3);
            const uint32_t off = SW128((uint32_t)((wid * 16 + rr) * 128 + kc * 2));
            ldsm_x4(qh[ks][0], qh[ks][1], qh[ks][2], qh[ks][3], sb + off);
            ldsm_x4(ql[ks][0], ql[ks][1], ql[ks][2], ql[ks][3], sb + 8192 + off);
        }
    }
    __syncthreads();

    const int rquad = lane >> 2;
    const int c2    = (lane & 3) << 1;
    const int rowa  = wid * 16 + rquad;

    float m_a = -INFINITY, m_b = -INFINITY, l_a = 0.f, l_b = 0.f;
    float o[8][4];
    #pragma unroll
    for (int i = 0; i < 8; i++)
        #pragma unroll
        for (int j = 0; j < 4; j++) o[i][j] = 0.f;

    const int nkv = (t0 >> 6) + 1;
    for (int kt = 0; kt < nkv; kt++) {
        const int s0 = kt << 6;
        if (kt) __syncthreads();
        {
            const size_t rowbase = ((size_t)b * Tc + s0) * QKVC;
            const int kcol = NHc * DHc + h * DHc;
            const int vcol = 2 * NHc * DHc;
            #pragma unroll
            for (int i = 0; i < 4; i++) {
                const int idx = tid + (i << 7);
                const int row = idx >> 3, ch = (idx & 7) << 4;
                const uint32_t off = SW128((uint32_t)(row * 128 + ch));
                const char* rh = reinterpret_cast<const char*>(
                    g_qkv_hi + rowbase + (size_t)row * QKVC);
                const char* rl = reinterpret_cast<const char*>(
                    g_qkv_lo + rowbase + (size_t)row * QKVC);
                *reinterpret_cast<uint4*>(smem + AT_KH + off) =
                    *reinterpret_cast<const uint4*>(rh + kcol * 2 + ch);
                *reinterpret_cast<uint4*>(smem + AT_KL + off) =
                    *reinterpret_cast<const uint4*>(rl + kcol * 2 + ch);
                *reinterpret_cast<uint4*>(smem + AT_VH + off) =
                    *reinterpret_cast<const uint4*>(rh + vcol * 2 + ch);
                *reinterpret_cast<uint4*>(smem + AT_VL + off) =
                    *reinterpret_cast<const uint4*>(rl + vcol * 2 + ch);
            }
        }
        __syncthreads();

        float sf[8][4];
        #pragma unroll
        for (int i = 0; i < 8; i++)
            #pragma unroll
            for (int j = 0; j < 4; j++) sf[i][j] = 0.f;

        #pragma unroll
        for (int ks = 0; ks < 4; ks++) {
            const int nr = (lane & 7) + ((lane >> 4) << 3);
            const int kc = (ks << 4) + ((lane >> 3) & 1) * 8;
            #pragma unroll
            for (int pp = 0; pp < 4; pp++) {
                const uint32_t off = SW128((uint32_t)((pp * 16 + nr) * 128 + kc * 2));
                uint32_t kh0, kh1, kh2, kh3, kl0, kl1, kl2, kl3;
                ldsm_x4(kh0, kh1, kh2, kh3, sb + AT_KH + off);
                ldsm_x4(kl0, kl1, kl2, kl3, sb + AT_KL + off);
                uint32_t b0h[2] = {kh0, kh1}, b1h[2] = {kh2, kh3};
                uint32_t b0l[2] = {kl0, kl1}, b1l[2] = {kl2, kl3};
                mma_bf16(sf[2*pp],   qh[ks], b0h);
                mma_bf16(sf[2*pp],   qh[ks], b0l);
                mma_bf16(sf[2*pp],   ql[ks], b0h);
                mma_bf16(sf[2*pp+1], qh[ks], b1h);
                mma_bf16(sf[2*pp+1], qh[ks], b1l);
                mma_bf16(sf[2*pp+1], ql[ks], b1h);
            }
        }

        const bool diag = (s0 == t0);
        #pragma unroll
        for (int nb = 0; nb < 8; nb++) {
            #pragma unroll
            for (int e = 0; e < 4; e++) {
                float sv = sf[nb][e] * 0.125f;
                if (diag) {
                    const int col = nb * 8 + c2 + (e & 1);
                    const int row = rowa + ((e >> 1) << 3);
                    if (col > row) sv = -INFINITY;
                }
                sf[nb][e] = sv;
            }
        }

        float ma_t = -INFINITY, mb_t = -INFINITY;
        #pragma unroll
        for (int nb = 0; nb < 8; nb++) {
            ma_t = fmaxf(ma_t, fmaxf(sf[nb][0], sf[nb][1]));
            mb_t = fmaxf(mb_t, fmaxf(sf[nb][2], sf[nb][3]));
        }
        ma_t = fmaxf(ma_t, __shfl_xor_sync(0xffffffffu, ma_t, 1));
        ma_t = fmaxf(ma_t, __shfl_xor_sync(0xffffffffu, ma_t, 2));
        mb_t = fmaxf(mb_t, __shfl_xor_sync(0xffffffffu, mb_t, 1));
        mb_t = fmaxf(mb_t, __shfl_xor_sync(0xffffffffu, mb_t, 2));

        const float mna = fmaxf(m_a, ma_t);
        const float mnb = fmaxf(m_b, mb_t);
        const float alpha_a = __expf(m_a - mna);
        const float alpha_b = __expf(m_b - mnb);
        m_a = mna; m_b = mnb;

        float sa = 0.f, sb_ = 0.f;
        #pragma unroll
        for (int nb = 0; nb < 8; nb++) {
            sf[nb][0] = __expf(sf[nb][0] - mna);
            sf[nb][1] = __expf(sf[nb][1] - mna);
            sf[nb][2] = __expf(sf[nb][2] - mnb);
            sf[nb][3] = __expf(sf[nb][3] - mnb);
            sa  += sf[nb][0] + sf[nb][1];
            sb_ += sf[nb][2] + sf[nb][3];
        }
        sa  += __shfl_xor_sync(0xffffffffu, sa, 1);
        sa  += __shfl_xor_sync(0xffffffffu, sa, 2);
        sb_ += __shfl_xor_sync(0xffffffffu, sb_, 1);
        sb_ += __shfl_xor_sync(0xffffffffu, sb_, 2);
        l_a = l_a * alpha_a + sa;
        l_b = l_b * alpha_b + sb_;
        #pragma unroll
        for (int db = 0; db < 8; db++) {
            o[db][0] *= alpha_a; o[db][1] *= alpha_a;
            o[db][2] *= alpha_b; o[db][3] *= alpha_b;
        }

        #pragma unroll
        for (int kb = 0; kb < 4; kb++) {
            uint32_t pa_h[4], pa_l[4];
            split2(sf[2*kb][0],   sf[2*kb][1],   pa_h[0], pa_l[0]);
            split2(sf[2*kb][2],   sf[2*kb][3],   pa_h[1], pa_l[1]);
            split2(sf[2*kb+1][0], sf[2*kb+1][1], pa_h[2], pa_l[2]);
            split2(sf[2*kb+1][2], sf[2*kb+1][3], pa_h[3], pa_l[3]);

            const int vr = kb * 16 + ((lane >> 3) & 1) * 8 + (lane & 7);
            #pragma unroll
            for (int djp = 0; djp < 4; djp++) {
                const int d0 = djp * 16 + ((lane >> 4) << 3);
                const uint32_t off = SW128((uint32_t)(vr * 128 + d0 * 2));
                uint32_t vh0, vh1, vh2, vh3, vl0, vl1, vl2, vl3;
                ldsm_x4t(vh0, vh1, vh2, vh3, sb + AT_VH + off);
                ldsm_x4t(vl0, vl1, vl2, vl3, sb + AT_VL + off);
                uint32_t b0h[2] = {vh0, vh1}, b1h[2] = {vh2, vh3};
                uint32_t b0l[2] = {vl0, vl1}, b1l[2] = {vl2, vl3};
                mma_bf16(o[2*djp],   pa_h, b0h);
                mma_bf16(o[2*djp],   pa_h, b0l);
                mma_bf16(o[2*djp],   pa_l, b0h);
                mma_bf16(o[2*djp+1], pa_h, b1h);
                mma_bf16(o[2*djp+1], pa_h, b1l);
                mma_bf16(o[2*djp+1], pa_l, b1h);
            }
        }
    }

    const float ia = 1.f / l_a;
    const float ib = 1.f / l_b;
    const int tla = (qt << 6) + rowa;
    const size_t basea = (((size_t)b * NHc + h) * TDc + tla) * DHc;
    const size_t baseb = basea + 8 * DHc;
    #pragma unroll
    for (int db = 0; db < 8; db++) {
        *reinterpret_cast<float2*>(g_attn + basea + db * 8 + c2) =
            make_float2(o[db][0] * ia, o[db][1] * ia);
        *reinterpret_cast<float2*>(g_attn + baseb + db * 8 + c2) =
            make_float2(o[db][2] * ib, o[db][3] * ib);
    }
}

// ---------------- mean over heads -> bf16 planes ----------------------------
__global__ void mean_k(__nv_bfloat16* __restrict__ mhi, __nv_bfloat16* __restrict__ mlo)
{
    int i = blockIdx.x * blockDim.x + threadIdx.x;   // pair index
    if (i >= Bc * TDc * DHc / 2) return;
    int e0 = i * 2;
    int b = e0 / (TDc * DHc);
    int rem = e0 % (TDc * DHc);
    float s0 = 0.f, s1 = 0.f;
    #pragma unroll
    for (int h = 0; h < NHc; h++) {
        size_t base = ((size_t)(b * NHc + h) * TDc * DHc) + rem;
        s0 += g_attn[base];
        s1 += g_attn[base + 1];
    }
    uint32_t hv, lv;
    split2(s0 * 0.25f, s1 * 0.25f, hv, lv);
    *reinterpret_cast<uint32_t*>(mhi + e0) = hv;
    *reinterpret_cast<uint32_t*>(mlo + e0) = lv;
}

// ---------------- host orchestration ----------------------------------------
extern "C" void kernel_launch(void* const* d_in, const int* in_sizes, int n_in,
                              void* d_out, int out_size)
{
    const float* TF       = (const float*)d_in[0];
    const float* ce       = (const float*)d_in[1];
    const float* eg_Wa    = (const float*)d_in[2];
    const float* eg_ba    = (const float*)d_in[3];
    const float* eg_Wc    = (const float*)d_in[4];
    const float* eg_Wi    = (const float*)d_in[5];
    const float* eg_bi    = (const float*)d_in[6];
    const float* eg_Wg    = (const float*)d_in[7];
    const float* eg_bg    = (const float*)d_in[8];
    const float* eg_lng   = (const float*)d_in[9];
    const float* eg_lnb   = (const float*)d_in[10];
    const float* att_Wqkv = (const float*)d_in[11];
    const float* att_Wout = (const float*)d_in[12];
    const float* ag_W     = (const float*)d_in[13];
    const float* ag_b     = (const float*)d_in[14];
    const float* aln_g    = (const float*)d_in[15];
    const float* aln_b    = (const float*)d_in[16];
    const float* pg_Wa    = (const float*)d_in[17];
    const float* pg_ba    = (const float*)d_in[18];
    const float* pg_Wi    = (const float*)d_in[19];
    const float* pg_bi    = (const float*)d_in[20];
    const float* pg_Wg    = (const float*)d_in[21];
    const float* pg_bg    = (const float*)d_in[22];
    const float* pg_lng   = (const float*)d_in[23];
    const float* pg_lnb   = (const float*)d_in[24];
    const float* dg_W     = (const float*)d_in[25];
    const float* dg_b     = (const float*)d_in[26];
    const float* dln_g    = (const float*)d_in[27];
    const float* dln_b    = (const float*)d_in[28];

    float *ceproj, *buf1, *buf2, *enr, *d2, *dx, *dy;
    __nv_bfloat16 *tfh, *tfl, *ceh, *cel, *p1h, *p1l, *p2h, *p2l;
    __nv_bfloat16 *qkvh, *qkvl, *math_, *matl, *wh, *wl;
    cudaGetSymbolAddress((void**)&ceproj, g_ceproj);
    cudaGetSymbolAddress((void**)&buf1,   g_buf1);
    cudaGetSymbolAddress((void**)&buf2,   g_buf2);
    cudaGetSymbolAddress((void**)&enr,    g_enr);
    cudaGetSymbolAddress((void**)&d2,     g_d2);
    cudaGetSymbolAddress((void**)&dx,     g_dx);
    cudaGetSymbolAddress((void**)&dy,     g_dy);
    cudaGetSymbolAddress((void**)&tfh,    g_tf_hi);
    cudaGetSymbolAddress((void**)&tfl,    g_tf_lo);
    cudaGetSymbolAddress((void**)&ceh,    g_ce_hi);
    cudaGetSymbolAddress((void**)&cel,    g_ce_lo);
    cudaGetSymbolAddress((void**)&p1h,    g_p1_hi);
    cudaGetSymbolAddress((void**)&p1l,    g_p1_lo);
    cudaGetSymbolAddress((void**)&p2h,    g_p2_hi);
    cudaGetSymbolAddress((void**)&p2l,    g_p2_lo);
    cudaGetSymbolAddress((void**)&qkvh,   g_qkv_hi);
    cudaGetSymbolAddress((void**)&qkvl,   g_qkv_lo);
    cudaGetSymbolAddress((void**)&math_,  g_mat_hi);
    cudaGetSymbolAddress((void**)&matl,   g_mat_lo);
    cudaGetSymbolAddress((void**)&wh,     g_w_hi);
    cudaGetSymbolAddress((void**)&wl,     g_w_lo);

    static int attr_set = 0;
    if (!attr_set) {
        cudaFuncSetAttribute(mma_gemm_k, cudaFuncAttributeMaxDynamicSharedMemorySize,
                             GS_TOTAL);
        attr_set = 1;
    }

    const int Menc = Bc * Tc;     // 65536
    const int Mdec = Bc * TDc;    // 16384

    auto conv = [&](const float* x, __nv_bfloat16* hi, __nv_bfloat16* lo, int n) {
        conv_k<<<(n / 4 + 255) / 256, 256>>>(x, hi, lo, n / 4);
    };
    auto gemm = [&](const __nv_bfloat16* Xh, const __nv_bfloat16* Xl,
                    const __nv_bfloat16* Wh, const __nv_bfloat16* Wl,
                    const float* bias, float* Y, int M, int N, int K, int act,
                    const float* rowadd,
                    __nv_bfloat16* Yhi = nullptr, __nv_bfloat16* Ylo = nullptr) {
        dim3 grid((N + 63) / 64, (M + 127) / 128);
        mma_gemm_k<<<grid, 256, GS_TOTAL>>>(Xh, Xl, Wh, Wl, bias, Y, M, N, K, act,
                                            rowadd, Yhi, Ylo);
    };

    // --- convert raw inputs and weights to planes (once per launch) ---
    conv(TF, tfh, tfl, Menc * Hc);
    conv(ce, ceh, cel, Bc * Hc);
    conv(eg_Wa,    wh + O_Wa,   wl + O_Wa,   Hc * Hc);
    conv(eg_Wc,    wh + O_Wc,   wl + O_Wc,   Hc * Hc);
    conv(eg_Wi,    wh + O_Wi,   wl + O_Wi,   Hc * Hc);
    conv(eg_Wg,    wh + O_Wg,   wl + O_Wg,   2 * Hc * Hc);
    conv(att_Wqkv, wh + O_QKV,  wl + O_QKV,  QKVC * Hc);
    conv(att_Wout, wh + O_WOUT, wl + O_WOUT, Hc * DHc);
    conv(ag_W,     wh + O_AG,   wl + O_AG,   2 * Hc * Hc);
    conv(pg_Wa,    wh + O_PGWA, wl + O_PGWA, Hc * Hc);
    conv(pg_Wi,    wh + O_PGWI, wl + O_PGWI, Hc * Hc);
    conv(pg_Wg,    wh + O_PGWG, wl + O_PGWG, 2 * Hc * Hc);
    conv(dg_W,     wh + O_DG,   wl + O_DG,   2 * Hc * Hc);

    // --- encoder GLU block ---
    gemm(ceh, cel, wh + O_Wc, wl + O_Wc, nullptr, ceproj, Bc, Hc, Hc, 0, nullptr);
    gemm(tfh, tfl, wh + O_Wa, wl + O_Wa, eg_ba, nullptr, Menc, Hc, Hc, 1, ceproj,
         p1h, p1l);
    gemm(p1h, p1l, wh + O_Wi, wl + O_Wi, eg_bi, nullptr, Menc, Hc, Hc, 0, nullptr,
         p2h, p2l);
    gemm(p2h, p2l, wh + O_Wg, wl + O_Wg, eg_bg, buf2, Menc, 2 * Hc, Hc, 0, nullptr);
    glu_k<<<Menc, 256>>>(buf2, buf1, Menc);
    ln_k<<<Menc / 8, 256>>>(buf1, TF, eg_lng, eg_lnb, enr, p1h, p1l, Menc, 0);

    // --- attention (decoder queries only) ---
    gemm(p1h, p1l, wh + O_QKV, wl + O_QKV, nullptr, nullptr, Menc, QKVC, Hc, 0,
         nullptr, qkvh, qkvl);
    attn_mma_k<<<dim3(TDc / 64, NHc, Bc), 128>>>();
    mean_k<<<(Bc * TDc * DHc / 2 + 255) / 256, 256>>>(math_, matl);
    gemm(math_, matl, wh + O_WOUT, wl + O_WOUT, nullptr, nullptr, Mdec, Hc, DHc, 0,
         nullptr, p2h, p2l);

    // --- decoder ---
    gemm(p2h, p2l, wh + O_AG, wl + O_AG, ag_b, d2, Mdec, 2 * Hc, Hc, 0, nullptr);
    glu_k<<<Mdec, 256>>>(d2, dx, Mdec);
    ln_k<<<Mdec / 8, 256>>>(dx, enr, aln_g, aln_b, dy, p1h, p1l, Mdec, 1);

    gemm(p1h, p1l, wh + O_PGWA, wl + O_PGWA, pg_ba, nullptr, Mdec, Hc, Hc, 1,
         nullptr, p2h, p2l);
    gemm(p2h, p2l, wh + O_PGWI, wl + O_PGWI, pg_bi, nullptr, Mdec, Hc, Hc, 0,
         nullptr, p1h, p1l);
    gemm(p1h, p1l, wh + O_PGWG, wl + O_PGWG, pg_bg, d2, Mdec, 2 * Hc, Hc, 0, nullptr);
    glu_k<<<Mdec, 256>>>(d2, dx, Mdec);
    ln_k<<<Mdec / 8, 256>>>(dx, dy, pg_lng, pg_lnb, nullptr, p2h, p2l, Mdec, 0);

    gemm(p2h, p2l, wh + O_DG, wl + O_DG, dg_b, d2, Mdec, 2 * Hc, Hc, 0, nullptr);
    glu_k<<<Mdec, 256>>>(d2, dx, Mdec);
    ln_k<<<Mdec / 8, 256>>>(dx, TF, dln_g, dln_b, (float*)d_out, nullptr, nullptr,
                            Mdec, 1);
}

// round 11
// speedup vs baseline: 2.0063x; 1.2180x over previous
#include <cuda_runtime.h>
#include <cuda_bf16.h>
#include <math.h>
#include <stdint.h>

// Problem constants
#define Bc   64
#define Tc   1024
#define Hc   256
#define NHc  4
#define DHc  64
#define ELc  768
#define TDc  256           // T - EL
#define QKVC 576           // (2*NH+1)*DH

// ---------------- scratch (device globals; no allocation allowed) -----------
__device__ float g_ceproj[Bc * Hc];
__device__ float g_buf2[(size_t)Bc * Tc * 2 * Hc];
__device__ float g_enr [Bc * Tc * Hc];
__device__ float g_attn[Bc * NHc * TDc * DHc];
__device__ float g_d2[Bc * TDc * 2 * Hc];
__device__ float g_dy[Bc * TDc * Hc];

// bf16 hi/lo plane buffers
__device__ __nv_bfloat16 g_tf_hi[(size_t)Bc * Tc * Hc];
__device__ __nv_bfloat16 g_tf_lo[(size_t)Bc * Tc * Hc];
__device__ __nv_bfloat16 g_ce_hi[Bc * Hc];
__device__ __nv_bfloat16 g_ce_lo[Bc * Hc];
__device__ __nv_bfloat16 g_p1_hi[(size_t)Bc * Tc * Hc];
__device__ __nv_bfloat16 g_p1_lo[(size_t)Bc * Tc * Hc];
__device__ __nv_bfloat16 g_p2_hi[(size_t)Bc * Tc * Hc];
__device__ __nv_bfloat16 g_p2_lo[(size_t)Bc * Tc * Hc];
__device__ __nv_bfloat16 g_qkv_hi[(size_t)Bc * Tc * QKVC];
__device__ __nv_bfloat16 g_qkv_lo[(size_t)Bc * Tc * QKVC];
__device__ __nv_bfloat16 g_mat_hi[Bc * TDc * DHc];
__device__ __nv_bfloat16 g_mat_lo[Bc * TDc * DHc];
#define WTOT 1015808
__device__ __nv_bfloat16 g_w_hi[WTOT];
__device__ __nv_bfloat16 g_w_lo[WTOT];
// weight plane offsets (elements)
#define O_Wa    0
#define O_Wc    65536
#define O_Wi    131072
#define O_Wg    196608
#define O_QKV   327680
#define O_WOUT  475136
#define O_AG    491520
#define O_PGWA  622592
#define O_PGWI  688128
#define O_PGWG  753664
#define O_DG    884736

// ======================= helpers ============================================
__device__ __forceinline__ uint32_t smem_to_u32(const void* p) {
    uint32_t a;
    asm("{ .reg .u64 t; cvta.to.shared.u64 t, %1; cvt.u32.u64 %0, t; }"
        : "=r"(a) : "l"(p));
    return a;
}
#define SW128(o) ((o) ^ (((o) >> 3) & 0x70))

#define CP_ASYNC16(dst, src) \
    asm volatile("cp.async.cg.shared.global [%0], [%1], 16;" \
        :: "r"(dst), "l"(src))
#define CP_COMMIT() asm volatile("cp.async.commit_group;" ::: "memory")
#define CP_WAIT1()  asm volatile("cp.async.wait_group 1;" ::: "memory")
#define CP_WAIT0()  asm volatile("cp.async.wait_group 0;" ::: "memory")

__device__ __forceinline__ uint32_t pack_bf16(float a, float b) {
    __nv_bfloat162 h = __floats2bfloat162_rn(a, b);
    return *reinterpret_cast<uint32_t*>(&h);
}
__device__ __forceinline__ void split2(float x, float y, uint32_t& hi, uint32_t& lo) {
    float xh = __bfloat162float(__float2bfloat16(x));
    float yh = __bfloat162float(__float2bfloat16(y));
    hi = pack_bf16(x, y);
    lo = pack_bf16(x - xh, y - yh);
}

__device__ __forceinline__ void ldsm_x4(uint32_t& r0, uint32_t& r1,
                                        uint32_t& r2, uint32_t& r3, uint32_t a) {
    asm volatile("ldmatrix.sync.aligned.m8n8.x4.shared.b16 {%0,%1,%2,%3}, [%4];"
        : "=r"(r0), "=r"(r1), "=r"(r2), "=r"(r3) : "r"(a));
}
__device__ __forceinline__ void ldsm_x4t(uint32_t& r0, uint32_t& r1,
                                         uint32_t& r2, uint32_t& r3, uint32_t a) {
    asm volatile("ldmatrix.sync.aligned.m8n8.x4.trans.shared.b16 {%0,%1,%2,%3}, [%4];"
        : "=r"(r0), "=r"(r1), "=r"(r2), "=r"(r3) : "r"(a));
}
__device__ __forceinline__ void mma_bf16(float* c, const uint32_t* a, const uint32_t* b) {
    asm volatile(
        "mma.sync.aligned.m16n8k16.row.col.f32.bf16.bf16.f32 "
        "{%0,%1,%2,%3}, {%4,%5,%6,%7}, {%8,%9}, {%0,%1,%2,%3};"
        : "+f"(c[0]), "+f"(c[1]), "+f"(c[2]), "+f"(c[3])
        : "r"(a[0]), "r"(a[1]), "r"(a[2]), "r"(a[3]), "r"(b[0]), "r"(b[1]));
}

// ---------------- fp32 -> bf16 hi/lo plane conversion -----------------------
__global__ void conv_k(const float* __restrict__ x, __nv_bfloat16* __restrict__ hi,
                       __nv_bfloat16* __restrict__ lo, int n4)
{
    int i = blockIdx.x * blockDim.x + threadIdx.x;
    if (i >= n4) return;
    float4 v = reinterpret_cast<const float4*>(x)[i];
    uint32_t h0, l0, h1, l1;
    split2(v.x, v.y, h0, l0);
    split2(v.z, v.w, h1, l1);
    reinterpret_cast<uint2*>(hi)[i] = make_uint2(h0, h1);
    reinterpret_cast<uint2*>(lo)[i] = make_uint2(l0, l1);
}

// ============ HMMA GEMM on pre-split planes, cp.async 2-stage pipeline ======
// Y[M,N] = X[M,K] @ W[N,K]^T. hi*hi + hi*lo + lo*hi (error ~2^-16).
// CTA tile 128x64, 8 warps, 2 stages x 48KB smem, 2 CTAs/SM.
#define GS_A_HI 0
#define GS_A_LO 16384
#define GS_B_HI 32768
#define GS_B_LO 40960
#define GS_STAGE 49152
#define GS_TOTAL 98304

__global__ void __launch_bounds__(256, 2)
mma_gemm_k(const __nv_bfloat16* __restrict__ Xhi, const __nv_bfloat16* __restrict__ Xlo,
           const __nv_bfloat16* __restrict__ Whi, const __nv_bfloat16* __restrict__ Wlo,
           const float* __restrict__ bias, float* __restrict__ Y,
           int M, int N, int K, int act, const float* __restrict__ rowadd,
           __nv_bfloat16* __restrict__ Yhi, __nv_bfloat16* __restrict__ Ylo)
{
    extern __shared__ char smem[];
    const uint32_t sb = smem_to_u32(smem);
    const int tid = threadIdx.x;
    const int wid = tid >> 5, lane = tid & 31;
    const int warp_m = wid >> 2;       // 0..1
    const int warp_n = wid & 3;        // 0..3
    const int row0 = blockIdx.y << 7;
    const int col0 = blockIdx.x << 6;  // 64-wide N tile

    // loader thread mapping (8 threads x 16B per 128B row)
    const int lr = tid >> 3;            // 0..31
    const int lch = (tid & 7) << 4;     // byte offset 0..112

    auto stage_load = [&](int s, int k0) {
        const uint32_t base = sb + s * GS_STAGE;
        #pragma unroll
        for (int i = 0; i < 4; i++) {
            const int row = lr + (i << 5);
            const int arow = min(row0 + row, M - 1);
            const uint32_t off = SW128((uint32_t)(row * 128 + lch));
            CP_ASYNC16(base + GS_A_HI + off,
                reinterpret_cast<const char*>(Xhi + (size_t)arow * K + k0) + lch);
            CP_ASYNC16(base + GS_A_LO + off,
                reinterpret_cast<const char*>(Xlo + (size_t)arow * K + k0) + lch);
        }
        #pragma unroll
        for (int i = 0; i < 2; i++) {
            const int row = lr + (i << 5);
            const int brow = min(col0 + row, N - 1);
            const uint32_t off = SW128((uint32_t)(row * 128 + lch));
            CP_ASYNC16(base + GS_B_HI + off,
                reinterpret_cast<const char*>(Whi + (size_t)brow * K + k0) + lch);
            CP_ASYNC16(base + GS_B_LO + off,
                reinterpret_cast<const char*>(Wlo + (size_t)brow * K + k0) + lch);
        }
        CP_COMMIT();
    };

    float acc[4][2][4] = {};
    const int nchunks = K >> 6;

    stage_load(0, 0);

    for (int c = 0; c < nchunks; c++) {
        if (c + 1 < nchunks) {
            stage_load((c + 1) & 1, (c + 1) << 6);
            CP_WAIT1();
        } else {
            CP_WAIT0();
        }
        __syncthreads();

        const uint32_t sbase = sb + (c & 1) * GS_STAGE;

        #pragma unroll
        for (int ks = 0; ks < 4; ks++) {
            const int kk = ks << 4;

            uint32_t ah[4][4], al[4][4], bh[2][2], bl[2][2];
            {
                const int rr = (lane & 7) + ((lane >> 3) & 1) * 8;
                const int kc = kk + ((lane >> 4) << 3);
                #pragma unroll
                for (int mt = 0; mt < 4; mt++) {
                    const uint32_t off =
                        SW128((uint32_t)((warp_m * 64 + mt * 16 + rr) * 128 + kc * 2));
                    ldsm_x4(ah[mt][0], ah[mt][1], ah[mt][2], ah[mt][3],
                            sbase + GS_A_HI + off);
                    ldsm_x4(al[mt][0], al[mt][1], al[mt][2], al[mt][3],
                            sbase + GS_A_LO + off);
                }
            }
            {
                const int nr = (lane & 7) + ((lane >> 4) << 3);
                const int kc = kk + ((lane >> 3) & 1) * 8;
                const uint32_t off =
                    SW128((uint32_t)((warp_n * 16 + nr) * 128 + kc * 2));
                uint32_t r0, r1, r2, r3;
                ldsm_x4(r0, r1, r2, r3, sbase + GS_B_HI + off);
                bh[0][0] = r0; bh[0][1] = r1; bh[1][0] = r2; bh[1][1] = r3;
                ldsm_x4(r0, r1, r2, r3, sbase + GS_B_LO + off);
                bl[0][0] = r0; bl[0][1] = r1; bl[1][0] = r2; bl[1][1] = r3;
            }

            #pragma unroll
            for (int mt = 0; mt < 4; mt++)
                #pragma unroll
                for (int nt = 0; nt < 2; nt++) {
                    mma_bf16(acc[mt][nt], ah[mt], bh[nt]);
                    mma_bf16(acc[mt][nt], ah[mt], bl[nt]);
                    mma_bf16(acc[mt][nt], al[mt], bh[nt]);
                }
        }
        __syncthreads();   // stage may be rewritten by prefetch 2 chunks ahead
    }

    const int r_hi  = lane >> 2;
    const int cpair = (lane & 3) << 1;

    #pragma unroll
    for (int mt = 0; mt < 4; mt++) {
        const int rbase = row0 + warp_m * 64 + mt * 16;
        #pragma unroll
        for (int h = 0; h < 2; h++) {
            const int grow = rbase + r_hi + h * 8;
            if (grow >= M) continue;
            #pragma unroll
            for (int nt = 0; nt < 2; nt++) {
                const int gcol = col0 + warp_n * 16 + nt * 8 + cpair;
                if (gcol >= N) continue;
                float v0 = acc[mt][nt][2 * h];
                float v1 = acc[mt][nt][2 * h + 1];
                if (bias) { v0 += bias[gcol]; v1 += bias[gcol + 1]; }
                if (rowadd) {
                    const size_t rb = (size_t)(grow >> 10) * N;
                    v0 += rowadd[rb + gcol];
                    v1 += rowadd[rb + gcol + 1];
                }
                if (act == 1) {
                    v0 = v0 > 0.f ? v0 : expm1f(v0);
                    v1 = v1 > 0.f ? v1 : expm1f(v1);
                }
                if (Yhi) {
                    uint32_t hv, lv;
                    split2(v0, v1, hv, lv);
                    *reinterpret_cast<uint32_t*>(Yhi + (size_t)grow * N + gcol) = hv;
                    *reinterpret_cast<uint32_t*>(Ylo + (size_t)grow * N + gcol) = lv;
                }
                if (Y) {
                    *reinterpret_cast<float2*>(Y + (size_t)grow * N + gcol) =
                        make_float2(v0, v1);
                }
            }
        }
    }
}

// ---------------- fused [GLU +] residual + LayerNorm (N = 256) --------------
// If glusrc != null: a-row = glu(glusrc[r, c], glusrc[r, c+256]) (ld 512).
// Else: a-row = a[r, c] (ld 256).
__global__ void ln_k(const float* __restrict__ a, const float* __restrict__ glusrc,
                     const float* __restrict__ resid,
                     const float* __restrict__ g, const float* __restrict__ b,
                     float* __restrict__ out,
                     __nv_bfloat16* __restrict__ ohi, __nv_bfloat16* __restrict__ olo,
                     int rows, int decmap)
{
    int warp = blockIdx.x * (blockDim.x >> 5) + (threadIdx.x >> 5);
    if (warp >= rows) return;
    int lane = threadIdx.x & 31;

    size_t arow = (size_t)warp * Hc;
    size_t rrow;
    if (decmap) {
        int bb = warp / TDc, tl = warp % TDc;
        rrow = ((size_t)bb * Tc + ELc + tl) * Hc;
    } else {
        rrow = arow;
    }

    float v[8];
    float s = 0.f, s2 = 0.f;
    #pragma unroll
    for (int i = 0; i < 4; i++) {
        int c = lane * 2 + 64 * i;
        float2 av;
        if (glusrc) {
            const float* gr = glusrc + (size_t)warp * 512;
            float2 aa = *reinterpret_cast<const float2*>(gr + c);
            float2 gg = *reinterpret_cast<const float2*>(gr + 256 + c);
            av.x = aa.x / (1.f + __expf(-gg.x));
            av.y = aa.y / (1.f + __expf(-gg.y));
        } else {
            av = *reinterpret_cast<const float2*>(a + arow + c);
        }
        float2 rv = *reinterpret_cast<const float2*>(resid + rrow + c);
        v[2*i]   = av.x + rv.x;
        v[2*i+1] = av.y + rv.y;
        s += v[2*i] + v[2*i+1];
        s2 += v[2*i] * v[2*i] + v[2*i+1] * v[2*i+1];
    }
    #pragma unroll
    for (int off = 16; off; off >>= 1) {
        s  += __shfl_xor_sync(0xffffffffu, s,  off);
        s2 += __shfl_xor_sync(0xffffffffu, s2, off);
    }
    float mu  = s  * (1.f / Hc);
    float var = s2 * (1.f / Hc) - mu * mu;
    float inv = rsqrtf(var + 1e-3f);
    #pragma unroll
    for (int i = 0; i < 4; i++) {
        int c = lane * 2 + 64 * i;
        float2 gv = *reinterpret_cast<const float2*>(g + c);
        float2 bv = *reinterpret_cast<const float2*>(b + c);
        float y0 = (v[2*i]   - mu) * inv * gv.x + bv.x;
        float y1 = (v[2*i+1] - mu) * inv * gv.y + bv.y;
        if (out)
            *reinterpret_cast<float2*>(out + arow + c) = make_float2(y0, y1);
        if (ohi) {
            uint32_t hv, lv;
            split2(y0, y1, hv, lv);
            *reinterpret_cast<uint32_t*>(ohi + arow + c) = hv;
            *reinterpret_cast<uint32_t*>(olo + arow + c) = lv;
        }
    }
}

// ============ HMMA flash attention (queries t in [EL, T)) ===================
#define AT_KH 0
#define AT_KL 8192
#define AT_VH 16384
#define AT_VL 24576

__global__ void __launch_bounds__(128, 3)
attn_mma_k()
{
    __shared__ char smem[32768];
    const uint32_t sb = smem_to_u32(smem);
    const int b = blockIdx.z, h = blockIdx.y, qt = blockIdx.x;
    const int t0 = ELc + (qt << 6);
    const int tid = threadIdx.x;
    const int wid = tid >> 5, lane = tid & 31;

    // ---- stage Q planes ----
    {
        const size_t rowbase = ((size_t)b * Tc + t0) * QKVC + h * DHc;
        #pragma unroll
        for (int i = 0; i < 4; i++) {
            const int idx = tid + (i << 7);
            const int row = idx >> 3, ch = (idx & 7) << 4;
            const uint32_t off = SW128((uint32_t)(row * 128 + ch));
            *reinterpret_cast<uint4*>(smem + off) =
                *reinterpret_cast<const uint4*>(
                    reinterpret_cast<const char*>(g_qkv_hi + rowbase + (size_t)row * QKVC) + ch);
            *reinterpret_cast<uint4*>(smem + 8192 + off) =
                *reinterpret_cast<const uint4*>(
                    reinterpret_cast<const char*>(g_qkv_lo + rowbase + (size_t)row * QKVC) + ch);
        }
    }
    __syncthreads();

    uint32_t qh[4][4], ql[4][4];
    {
        const int rr = (lane & 7) + ((lane >> 3) & 1) * 8;
        #pragma unroll
        for (int ks = 0; ks < 4; ks++) {
            const int kc = (ks << 4) + ((lane >> 4) << 3);
            const uint32_t off = SW128((uint32_t)((wid * 16 + rr) * 128 + kc * 2));
            ldsm_x4(qh[ks][0], qh[ks][1], qh[ks][2], qh[ks][3], sb + off);
            ldsm_x4(ql[ks][0], ql[ks][1], ql[ks][2], ql[ks][3], sb + 8192 + off);
        }
    }
    __syncthreads();

    const int rquad = lane >> 2;
    const int c2    = (lane & 3) << 1;
    const int rowa  = wid * 16 + rquad;

    float m_a = -INFINITY, m_b = -INFINITY, l_a = 0.f, l_b = 0.f;
    float o[8][4];
    #pragma unroll
    for (int i = 0; i < 8; i++)
        #pragma unroll
        for (int j = 0; j < 4; j++) o[i][j] = 0.f;

    const int nkv = (t0 >> 6) + 1;
    for (int kt = 0; kt < nkv; kt++) {
        const int s0 = kt << 6;
        if (kt) __syncthreads();
        {
            const size_t rowbase = ((size_t)b * Tc + s0) * QKVC;
            const int kcol = NHc * DHc + h * DHc;
            const int vcol = 2 * NHc * DHc;
            #pragma unroll
            for (int i = 0; i < 4; i++) {
                const int idx = tid + (i << 7);
                const int row = idx >> 3, ch = (idx & 7) << 4;
                const uint32_t off = SW128((uint32_t)(row * 128 + ch));
                const char* rh = reinterpret_cast<const char*>(
                    g_qkv_hi + rowbase + (size_t)row * QKVC);
                const char* rl = reinterpret_cast<const char*>(
                    g_qkv_lo + rowbase + (size_t)row * QKVC);
                *reinterpret_cast<uint4*>(smem + AT_KH + off) =
                    *reinterpret_cast<const uint4*>(rh + kcol * 2 + ch);
                *reinterpret_cast<uint4*>(smem + AT_KL + off) =
                    *reinterpret_cast<const uint4*>(rl + kcol * 2 + ch);
                *reinterpret_cast<uint4*>(smem + AT_VH + off) =
                    *reinterpret_cast<const uint4*>(rh + vcol * 2 + ch);
                *reinterpret_cast<uint4*>(smem + AT_VL + off) =
                    *reinterpret_cast<const uint4*>(rl + vcol * 2 + ch);
            }
        }
        __syncthreads();

        float sf[8][4];
        #pragma unroll
        for (int i = 0; i < 8; i++)
            #pragma unroll
            for (int j = 0; j < 4; j++) sf[i][j] = 0.f;

        #pragma unroll
        for (int ks = 0; ks < 4; ks++) {
            const int nr = (lane & 7) + ((lane >> 4) << 3);
            const int kc = (ks << 4) + ((lane >> 3) & 1) * 8;
            #pragma unroll
            for (int pp = 0; pp < 4; pp++) {
                const uint32_t off = SW128((uint32_t)((pp * 16 + nr) * 128 + kc * 2));
                uint32_t kh0, kh1, kh2, kh3, kl0, kl1, kl2, kl3;
                ldsm_x4(kh0, kh1, kh2, kh3, sb + AT_KH + off);
                ldsm_x4(kl0, kl1, kl2, kl3, sb + AT_KL + off);
                uint32_t b0h[2] = {kh0, kh1}, b1h[2] = {kh2, kh3};
                uint32_t b0l[2] = {kl0, kl1}, b1l[2] = {kl2, kl3};
                mma_bf16(sf[2*pp],   qh[ks], b0h);
                mma_bf16(sf[2*pp],   qh[ks], b0l);
                mma_bf16(sf[2*pp],   ql[ks], b0h);
                mma_bf16(sf[2*pp+1], qh[ks], b1h);
                mma_bf16(sf[2*pp+1], qh[ks], b1l);
                mma_bf16(sf[2*pp+1], ql[ks], b1h);
            }
        }

        const bool diag = (s0 == t0);
        #pragma unroll
        for (int nb = 0; nb < 8; nb++) {
            #pragma unroll
            for (int e = 0; e < 4; e++) {
                float sv = sf[nb][e] * 0.125f;
                if (diag) {
                    const int col = nb * 8 + c2 + (e & 1);
                    const int row = rowa + ((e >> 1) << 3);
                    if (col > row) sv = -INFINITY;
                }
                sf[nb][e] = sv;
            }
        }

        float ma_t = -INFINITY, mb_t = -INFINITY;
        #pragma unroll
        for (int nb = 0; nb < 8; nb++) {
            ma_t = fmaxf(ma_t, fmaxf(sf[nb][0], sf[nb][1]));
            mb_t = fmaxf(mb_t, fmaxf(sf[nb][2], sf[nb][3]));
        }
        ma_t = fmaxf(ma_t, __shfl_xor_sync(0xffffffffu, ma_t, 1));
        ma_t = fmaxf(ma_t, __shfl_xor_sync(0xffffffffu, ma_t, 2));
        mb_t = fmaxf(mb_t, __shfl_xor_sync(0xffffffffu, mb_t, 1));
        mb_t = fmaxf(mb_t, __shfl_xor_sync(0xffffffffu, mb_t, 2));

        const float mna = fmaxf(m_a, ma_t);
        const float mnb = fmaxf(m_b, mb_t);
        const float alpha_a = __expf(m_a - mna);
        const float alpha_b = __expf(m_b - mnb);
        m_a = mna; m_b = mnb;

        float sa = 0.f, sb_ = 0.f;
        #pragma unroll
        for (int nb = 0; nb < 8; nb++) {
            sf[nb][0] = __expf(sf[nb][0] - mna);
            sf[nb][1] = __expf(sf[nb][1] - mna);
            sf[nb][2] = __expf(sf[nb][2] - mnb);
            sf[nb][3] = __expf(sf[nb][3] - mnb);
            sa  += sf[nb][0] + sf[nb][1];
            sb_ += sf[nb][2] + sf[nb][3];
        }
        sa  += __shfl_xor_sync(0xffffffffu, sa, 1);
        sa  += __shfl_xor_sync(0xffffffffu, sa, 2);
        sb_ += __shfl_xor_sync(0xffffffffu, sb_, 1);
        sb_ += __shfl_xor_sync(0xffffffffu, sb_, 2);
        l_a = l_a * alpha_a + sa;
        l_b = l_b * alpha_b + sb_;
        #pragma unroll
        for (int db = 0; db < 8; db++) {
            o[db][0] *= alpha_a; o[db][1] *= alpha_a;
            o[db][2] *= alpha_b; o[db][3] *= alpha_b;
        }

        #pragma unroll
        for (int kb = 0; kb < 4; kb++) {
            uint32_t pa_h[4], pa_l[4];
            split2(sf[2*kb][0],   sf[2*kb][1],   pa_h[0], pa_l[0]);
            split2(sf[2*kb][2],   sf[2*kb][3],   pa_h[1], pa_l[1]);
            split2(sf[2*kb+1][0], sf[2*kb+1][1], pa_h[2], pa_l[2]);
            split2(sf[2*kb+1][2], sf[2*kb+1][3], pa_h[3], pa_l[3]);

            const int vr = kb * 16 + ((lane >> 3) & 1) * 8 + (lane & 7);
            #pragma unroll
            for (int djp = 0; djp < 4; djp++) {
                const int d0 = djp * 16 + ((lane >> 4) << 3);
                const uint32_t off = SW128((uint32_t)(vr * 128 + d0 * 2));
                uint32_t vh0, vh1, vh2, vh3, vl0, vl1, vl2, vl3;
                ldsm_x4t(vh0, vh1, vh2, vh3, sb + AT_VH + off);
                ldsm_x4t(vl0, vl1, vl2, vl3, sb + AT_VL + off);
                uint32_t b0h[2] = {vh0, vh1}, b1h[2] = {vh2, vh3};
                uint32_t b0l[2] = {vl0, vl1}, b1l[2] = {vl2, vl3};
                mma_bf16(o[2*djp],   pa_h, b0h);
                mma_bf16(o[2*djp],   pa_h, b0l);
                mma_bf16(o[2*djp],   pa_l, b0h);
                mma_bf16(o[2*djp+1], pa_h, b1h);
                mma_bf16(o[2*djp+1], pa_h, b1l);
                mma_bf16(o[2*djp+1], pa_l, b1h);
            }
        }
    }

    const float ia = 1.f / l_a;
    const float ib = 1.f / l_b;
    const int tla = (qt << 6) + rowa;
    const size_t basea = (((size_t)b * NHc + h) * TDc + tla) * DHc;
    const size_t baseb = basea + 8 * DHc;
    #pragma unroll
    for (int db = 0; db < 8; db++) {
        *reinterpret_cast<float2*>(g_attn + basea + db * 8 + c2) =
            make_float2(o[db][0] * ia, o[db][1] * ia);
        *reinterpret_cast<float2*>(g_attn + baseb + db * 8 + c2) =
            make_float2(o[db][2] * ib, o[db][3] * ib);
    }
}

// ---------------- mean over heads -> bf16 planes ----------------------------
__global__ void mean_k(__nv_bfloat16* __restrict__ mhi, __nv_bfloat16* __restrict__ mlo)
{
    int i = blockIdx.x * blockDim.x + threadIdx.x;   // pair index
    if (i >= Bc * TDc * DHc / 2) return;
    int e0 = i * 2;
    int b = e0 / (TDc * DHc);
    int rem = e0 % (TDc * DHc);
    float s0 = 0.f, s1 = 0.f;
    #pragma unroll
    for (int h = 0; h < NHc; h++) {
        size_t base = ((size_t)(b * NHc + h) * TDc * DHc) + rem;
        s0 += g_attn[base];
        s1 += g_attn[base + 1];
    }
    uint32_t hv, lv;
    split2(s0 * 0.25f, s1 * 0.25f, hv, lv);
    *reinterpret_cast<uint32_t*>(mhi + e0) = hv;
    *reinterpret_cast<uint32_t*>(mlo + e0) = lv;
}

// ---------------- host orchestration ----------------------------------------
extern "C" void kernel_launch(void* const* d_in, const int* in_sizes, int n_in,
                              void* d_out, int out_size)
{
    const float* TF       = (const float*)d_in[0];
    const float* ce       = (const float*)d_in[1];
    const float* eg_Wa    = (const float*)d_in[2];
    const float* eg_ba    = (const float*)d_in[3];
    const float* eg_Wc    = (const float*)d_in[4];
    const float* eg_Wi    = (const float*)d_in[5];
    const float* eg_bi    = (const float*)d_in[6];
    const float* eg_Wg    = (const float*)d_in[7];
    const float* eg_bg    = (const float*)d_in[8];
    const float* eg_lng   = (const float*)d_in[9];
    const float* eg_lnb   = (const float*)d_in[10];
    const float* att_Wqkv = (const float*)d_in[11];
    const float* att_Wout = (const float*)d_in[12];
    const float* ag_W     = (const float*)d_in[13];
    const float* ag_b     = (const float*)d_in[14];
    const float* aln_g    = (const float*)d_in[15];
    const float* aln_b    = (const float*)d_in[16];
    const float* pg_Wa    = (const float*)d_in[17];
    const float* pg_ba    = (const float*)d_in[18];
    const float* pg_Wi    = (const float*)d_in[19];
    const float* pg_bi    = (const float*)d_in[20];
    const float* pg_Wg    = (const float*)d_in[21];
    const float* pg_bg    = (const float*)d_in[22];
    const float* pg_lng   = (const float*)d_in[23];
    const float* pg_lnb   = (const float*)d_in[24];
    const float* dg_W     = (const float*)d_in[25];
    const float* dg_b     = (const float*)d_in[26];
    const float* dln_g    = (const float*)d_in[27];
    const float* dln_b    = (const float*)d_in[28];

    float *ceproj, *buf2, *enr, *d2, *dy;
    __nv_bfloat16 *tfh, *tfl, *ceh, *cel, *p1h, *p1l, *p2h, *p2l;
    __nv_bfloat16 *qkvh, *qkvl, *math_, *matl, *wh, *wl;
    cudaGetSymbolAddress((void**)&ceproj, g_ceproj);
    cudaGetSymbolAddress((void**)&buf2,   g_buf2);
    cudaGetSymbolAddress((void**)&enr,    g_enr);
    cudaGetSymbolAddress((void**)&d2,     g_d2);
    cudaGetSymbolAddress((void**)&dy,     g_dy);
    cudaGetSymbolAddress((void**)&tfh,    g_tf_hi);
    cudaGetSymbolAddress((void**)&tfl,    g_tf_lo);
    cudaGetSymbolAddress((void**)&ceh,    g_ce_hi);
    cudaGetSymbolAddress((void**)&cel,    g_ce_lo);
    cudaGetSymbolAddress((void**)&p1h,    g_p1_hi);
    cudaGetSymbolAddress((void**)&p1l,    g_p1_lo);
    cudaGetSymbolAddress((void**)&p2h,    g_p2_hi);
    cudaGetSymbolAddress((void**)&p2l,    g_p2_lo);
    cudaGetSymbolAddress((void**)&qkvh,   g_qkv_hi);
    cudaGetSymbolAddress((void**)&qkvl,   g_qkv_lo);
    cudaGetSymbolAddress((void**)&math_,  g_mat_hi);
    cudaGetSymbolAddress((void**)&matl,   g_mat_lo);
    cudaGetSymbolAddress((void**)&wh,     g_w_hi);
    cudaGetSymbolAddress((void**)&wl,     g_w_lo);

    static int attr_set = 0;
    if (!attr_set) {
        cudaFuncSetAttribute(mma_gemm_k, cudaFuncAttributeMaxDynamicSharedMemorySize,
                             GS_TOTAL);
        attr_set = 1;
    }

    const int Menc = Bc * Tc;     // 65536
    const int Mdec = Bc * TDc;    // 16384

    auto conv = [&](const float* x, __nv_bfloat16* hi, __nv_bfloat16* lo, int n) {
        conv_k<<<(n / 4 + 255) / 256, 256>>>(x, hi, lo, n / 4);
    };
    auto gemm = [&](const __nv_bfloat16* Xh, const __nv_bfloat16* Xl,
                    const __nv_bfloat16* Wh, const __nv_bfloat16* Wl,
                    const float* bias, float* Y, int M, int N, int K, int act,
                    const float* rowadd,
                    __nv_bfloat16* Yhi = nullptr, __nv_bfloat16* Ylo = nullptr) {
        dim3 grid((N + 63) / 64, (M + 127) / 128);
        mma_gemm_k<<<grid, 256, GS_TOTAL>>>(Xh, Xl, Wh, Wl, bias, Y, M, N, K, act,
                                            rowadd, Yhi, Ylo);
    };

    // --- convert raw inputs and weights to planes (once per launch) ---
    conv(TF, tfh, tfl, Menc * Hc);
    conv(ce, ceh, cel, Bc * Hc);
    conv(eg_Wa,    wh + O_Wa,   wl + O_Wa,   Hc * Hc);
    conv(eg_Wc,    wh + O_Wc,   wl + O_Wc,   Hc * Hc);
    conv(eg_Wi,    wh + O_Wi,   wl + O_Wi,   Hc * Hc);
    conv(eg_Wg,    wh + O_Wg,   wl + O_Wg,   2 * Hc * Hc);
    conv(att_Wqkv, wh + O_QKV,  wl + O_QKV,  QKVC * Hc);
    conv(att_Wout, wh + O_WOUT, wl + O_WOUT, Hc * DHc);
    conv(ag_W,     wh + O_AG,   wl + O_AG,   2 * Hc * Hc);
    conv(pg_Wa,    wh + O_PGWA, wl + O_PGWA, Hc * Hc);
    conv(pg_Wi,    wh + O_PGWI, wl + O_PGWI, Hc * Hc);
    conv(pg_Wg,    wh + O_PGWG, wl + O_PGWG, 2 * Hc * Hc);
    conv(dg_W,     wh + O_DG,   wl + O_DG,   2 * Hc * Hc);

    // --- encoder GLU block ---
    gemm(ceh, cel, wh + O_Wc, wl + O_Wc, nullptr, ceproj, Bc, Hc, Hc, 0, nullptr);
    gemm(tfh, tfl, wh + O_Wa, wl + O_Wa, eg_ba, nullptr, Menc, Hc, Hc, 1, ceproj,
         p1h, p1l);
    gemm(p1h, p1l, wh + O_Wi, wl + O_Wi, eg_bi, nullptr, Menc, Hc, Hc, 0, nullptr,
         p2h, p2l);
    gemm(p2h, p2l, wh + O_Wg, wl + O_Wg, eg_bg, buf2, Menc, 2 * Hc, Hc, 0, nullptr);
    ln_k<<<Menc / 8, 256>>>(nullptr, buf2, TF, eg_lng, eg_lnb, enr, p1h, p1l,
                            Menc, 0);

    // --- attention (decoder queries only) ---
    gemm(p1h, p1l, wh + O_QKV, wl + O_QKV, nullptr, nullptr, Menc, QKVC, Hc, 0,
         nullptr, qkvh, qkvl);
    attn_mma_k<<<dim3(TDc / 64, NHc, Bc), 128>>>();
    mean_k<<<(Bc * TDc * DHc / 2 + 255) / 256, 256>>>(math_, matl);
    gemm(math_, matl, wh + O_WOUT, wl + O_WOUT, nullptr, nullptr, Mdec, Hc, DHc, 0,
         nullptr, p2h, p2l);

    // --- decoder ---
    gemm(p2h, p2l, wh + O_AG, wl + O_AG, ag_b, d2, Mdec, 2 * Hc, Hc, 0, nullptr);
    ln_k<<<Mdec / 8, 256>>>(nullptr, d2, enr, aln_g, aln_b, dy, p1h, p1l, Mdec, 1);

    gemm(p1h, p1l, wh + O_PGWA, wl + O_PGWA, pg_ba, nullptr, Mdec, Hc, Hc, 1,
         nullptr, p2h, p2l);
    gemm(p2h, p2l, wh + O_PGWI, wl + O_PGWI, pg_bi, nullptr, Mdec, Hc, Hc, 0,
         nullptr, p1h, p1l);
    gemm(p1h, p1l, wh + O_PGWG, wl + O_PGWG, pg_bg, d2, Mdec, 2 * Hc, Hc, 0, nullptr);
    ln_k<<<Mdec / 8, 256>>>(nullptr, d2, dy, pg_lng, pg_lnb, nullptr, p2h, p2l,
                            Mdec, 0);

    gemm(p2h, p2l, wh + O_DG, wl + O_DG, dg_b, d2, Mdec, 2 * Hc, Hc, 0, nullptr);
    ln_k<<<Mdec / 8, 256>>>(nullptr, d2, TF, dln_g, dln_b, (float*)d_out,
                            nullptr, nullptr, Mdec, 1);
}